// round 10
// baseline (speedup 1.0000x reference)
#include <cuda_runtime.h>
#include <cuda_fp16.h>
#include <mma.h>
#include <math.h>
#include <stdint.h>

using namespace nvcuda;

#define DD 300
#define NCOLS 1800
#define KK2 320             // K padded to 320 (zero-padded)
#define MAXN 50000
#define MAXE 250000
#define MPAD 50048          // 391 * 128
#define STAGES 4
#define KT 32
#define NT (KK2 / KT)       // 10
#define SFST 608            // d_Sf row stride (floats): Q[0..300), Cd[304..604)
#define SHST 960            // d_Sh row stride (halves): K[0..300), V[320..620), Cs[640..940)

// ---- static scratch (allocation-free rule: __device__ globals) ----
__device__ __half d_Ah[(size_t)MPAD * KK2];    // [MPAD][320] fp16, pads stay 0
__device__ __half d_WhT[(size_t)1920 * KK2];   // [1920][320] Wbig^T fp16
__device__ float  d_Sf[(size_t)MPAD * SFST];   // fp32: Q | Cd
__device__ __half d_Sh[(size_t)MPAD * SHST];   // fp16: K | V | Cs
__device__ float  d_NLi[3 * DD];
__device__ float  d_NLj[3 * DD];
__device__ float  d_W2f[2 * DD];
__device__ float  d_c0[DD];
__device__ float  d_T8[8 * DD];
__device__ float  d_G8[8 * DD];
// CSR scratch
__device__ int  d_deg[MAXN];
__device__ int  d_rowptr[MAXN + 1];
__device__ int  d_cursor[MAXN];
__device__ int  d_blksum[256];
__device__ int2 d_edges[MAXE];

__device__ __forceinline__ float fast_tanh(float x) {
    float r;
    asm("tanh.approx.f32 %0, %1;" : "=f"(r) : "f"(x));
    return r;
}
__device__ __forceinline__ float4 h4tof4(uint2 u) {
    __half2 a = *(__half2*)&u.x, b = *(__half2*)&u.y;
    float2 fa = __half22float2(a), fb = __half22float2(b);
    return make_float4(fa.x, fa.y, fb.x, fb.y);
}

// ---------------- fold 1 ----------------
__global__ void fold1_kernel(const float* __restrict__ Wn, const float* __restrict__ Wxy,
                             const float* __restrict__ Wloc, const float* __restrict__ Wfus,
                             const float* __restrict__ vocab, const float* __restrict__ bxy,
                             const float* __restrict__ bn, const float* __restrict__ bobj,
                             const float* __restrict__ bloc, const float* __restrict__ bfus) {
    int c = blockIdx.x * blockDim.x + threadIdx.x;
    if (c >= DD) return;
    float nli0 = 0, nli1 = 0, nli2 = 0, nlj0 = 0, nlj1 = 0, nlj2 = 0;
    float w20 = 0, w21 = 0, c0 = 0;
    float t0 = 0, t1 = 0, t2 = 0, t3 = 0, t4 = 0, t5 = 0, t6 = 0;
    for (int k = 0; k < DD; k++) {
        float wl0 = Wloc[k * DD + c];
        float wl1 = Wloc[(DD + k) * DD + c];
        float wl2 = Wloc[(2 * DD + k) * DD + c];
        float wn0 = Wn[k], wn1 = Wn[DD + k], wn2 = Wn[2 * DD + k];
        nli0 = fmaf(wn0, wl1, nli0); nli1 = fmaf(wn1, wl1, nli1); nli2 = fmaf(wn2, wl1, nli2);
        nlj0 = fmaf(wn0, wl2, nlj0); nlj1 = fmaf(wn1, wl2, nlj1); nlj2 = fmaf(wn2, wl2, nlj2);
        w20 = fmaf(Wxy[k], wl0, w20); w21 = fmaf(Wxy[DD + k], wl0, w21);
        c0 = fmaf(bxy[k], wl0, c0);
        c0 = fmaf(bn[k], wl1 + wl2, c0);
        float wf0 = Wfus[k * DD + c];
        float wf1 = Wfus[(DD + k) * DD + c];
        t0 = fmaf(vocab[2 * DD + k], wf1, t0);
        t1 = fmaf(vocab[3 * DD + k], wf1, t1);
        t2 = fmaf(vocab[4 * DD + k], wf1, t2);
        t3 = fmaf(vocab[5 * DD + k], wf1, t3);
        t4 = fmaf(vocab[6 * DD + k], wf1, t4);
        t5 = fmaf(vocab[k], wf0, t5);
        t6 = fmaf(vocab[DD + k], wf0, t6);
    }
    d_NLi[0 * DD + c] = nli0; d_NLi[1 * DD + c] = nli1; d_NLi[2 * DD + c] = nli2;
    d_NLj[0 * DD + c] = nlj0; d_NLj[1 * DD + c] = nlj1; d_NLj[2 * DD + c] = nlj2;
    d_W2f[c] = w20; d_W2f[DD + c] = w21;
    d_c0[c] = c0 + bobj[c] + bloc[c];
    d_T8[0 * DD + c] = t0; d_T8[1 * DD + c] = t1; d_T8[2 * DD + c] = t2;
    d_T8[3 * DD + c] = t3; d_T8[4 * DD + c] = t4; d_T8[5 * DD + c] = t5;
    d_T8[6 * DD + c] = t6; d_T8[7 * DD + c] = bfus[c];
}

// ---------------- fold 2: G8 = T8 @ We ----------------
__global__ void fold2_kernel(const float* __restrict__ We) {
    int c = blockIdx.x * blockDim.x + threadIdx.x;
    if (c >= DD) return;
    float g[8] = {0, 0, 0, 0, 0, 0, 0, 0};
    for (int k = 0; k < DD; k++) {
        float w = We[k * DD + c];
        #pragma unroll
        for (int j = 0; j < 8; j++) g[j] = fmaf(d_T8[j * DD + k], w, g[j]);
    }
    #pragma unroll
    for (int j = 0; j < 8; j++) d_G8[j * DD + c] = g[j];
}

// ---------------- build A (fp16; pad entries never written, stay zero) ----------------
__global__ void buildA_kernel(const float* __restrict__ x, const float* __restrict__ nrm, int Nn) {
    int idx = blockIdx.x * blockDim.x + threadIdx.x;
    if (idx >= Nn * 304) return;
    int n = idx / 304, k = idx - n * 304;
    float v;
    if (k < DD) v = x[n * DD + k];
    else if (k < DD + 3) v = nrm[n * 3 + (k - DD)];
    else v = 1.0f;
    d_Ah[(size_t)n * KK2 + k] = __float2half_rn(v);
}

// ---------------- build WhT [c][k] fp16 ----------------
__global__ void buildW_kernel(const float* __restrict__ Wq, const float* __restrict__ Wk,
                              const float* __restrict__ Wv, const float* __restrict__ Wskip,
                              const float* __restrict__ Wobj, const float* __restrict__ bq,
                              const float* __restrict__ bk, const float* __restrict__ bv,
                              const float* __restrict__ bskip) {
    int idx = blockIdx.x * blockDim.x + threadIdx.x;
    if (idx >= NCOLS * 304) return;
    int c = idx / 304, k = idx - c * 304;
    int b = c / DD, cc = c - b * DD;
    float v = 0.0f;
    if (k < DD) {
        if (b == 0) v = Wq[k * DD + cc];
        else if (b == 1) v = Wk[k * DD + cc];
        else if (b == 2) v = Wv[k * DD + cc];
        else if (b == 3) v = Wskip[k * DD + cc];
        else if (b == 4) v = Wobj[k * DD + cc] - Wobj[(DD + k) * DD + cc];
        else v = Wobj[(DD + k) * DD + cc];
    } else if (k < DD + 3) {
        int r = k - DD;
        if (b == 4) v = d_NLi[r * DD + cc];
        else if (b == 5) v = d_NLj[r * DD + cc];
    } else {
        if (b == 0) v = bq[cc];
        else if (b == 1) v = bk[cc];
        else if (b == 2) v = bv[cc];
        else if (b == 3) v = bskip[cc];
        else if (b == 4) v = d_c0[cc];
    }
    d_WhT[(size_t)c * KK2 + k] = __float2half_rn(v);
}

// ---------------- node GEMM (fp16 wmma m16n16k16, cp.async 4-stage, routed epilogue) ----
__global__ void __launch_bounds__(256, 2) gemm_fp16_kernel(float* __restrict__ out, int Nn) {
    extern __shared__ __half sm[];
    __half (*As)[128][40] = (__half (*)[128][40])sm;
    __half (*Bs)[128][40] = (__half (*)[128][40])(sm + STAGES * 128 * 40);
    float (*stage)[132] = (float (*)[132])sm;

    int tid = threadIdx.x;
    int wid = tid >> 5;
    int wm = wid >> 2;
    int wn = wid & 3;
    int row0 = blockIdx.y * 128, col0 = blockIdx.x * 128;

    wmma::fragment<wmma::accumulator, 16, 16, 16, float> acc[4][2];
    #pragma unroll
    for (int i = 0; i < 4; i++)
        #pragma unroll
        for (int j = 0; j < 2; j++) wmma::fill_fragment(acc[i][j], 0.0f);

    auto loadStage = [&](int st, int kt) {
        #pragma unroll
        for (int u = 0; u < 2; u++) {
            int idx = tid + 256 * u;
            int row = idx >> 2, seg = idx & 3;
            const __half* ga = &d_Ah[(size_t)(row0 + row) * KK2 + kt + seg * 8];
            uint32_t da = (uint32_t)__cvta_generic_to_shared(&As[st][row][seg * 8]);
            asm volatile("cp.async.cg.shared.global [%0], [%1], 16;" :: "r"(da), "l"(ga));
            const __half* gb = &d_WhT[(size_t)(col0 + row) * KK2 + kt + seg * 8];
            uint32_t db = (uint32_t)__cvta_generic_to_shared(&Bs[st][row][seg * 8]);
            asm volatile("cp.async.cg.shared.global [%0], [%1], 16;" :: "r"(db), "l"(gb));
        }
    };

    #pragma unroll
    for (int i = 0; i < STAGES - 1; i++) {
        loadStage(i, i * KT);
        asm volatile("cp.async.commit_group;");
    }

    for (int s = 0; s < NT; s++) {
        asm volatile("cp.async.wait_group %0;" :: "n"(STAGES - 2));
        __syncthreads();
        int ld = s + STAGES - 1;
        if (ld < NT) loadStage(ld & (STAGES - 1), ld * KT);
        asm volatile("cp.async.commit_group;");

        int st = s & (STAGES - 1);
        #pragma unroll
        for (int ks = 0; ks < 2; ks++) {
            int k0 = ks * 16;
            wmma::fragment<wmma::matrix_b, 16, 16, 16, __half, wmma::col_major> bf[2];
            #pragma unroll
            for (int j = 0; j < 2; j++)
                wmma::load_matrix_sync(bf[j], &Bs[st][wn * 32 + j * 16][k0], 40);
            #pragma unroll
            for (int i = 0; i < 4; i++) {
                wmma::fragment<wmma::matrix_a, 16, 16, 16, __half, wmma::row_major> af;
                wmma::load_matrix_sync(af, &As[st][wm * 64 + i * 16][k0], 40);
                #pragma unroll
                for (int j = 0; j < 2; j++)
                    wmma::mma_sync(acc[i][j], af, bf[j], acc[i][j]);
            }
        }
    }

    asm volatile("cp.async.wait_group 0;");
    __syncthreads();
    #pragma unroll
    for (int i = 0; i < 4; i++)
        #pragma unroll
        for (int j = 0; j < 2; j++)
            wmma::store_matrix_sync(&stage[wm * 64 + i * 16][wn * 32 + j * 16],
                                    acc[i][j], 132, wmma::mem_row_major);
    __syncthreads();

    #pragma unroll
    for (int it = 0; it < 16; it++) {
        int idx = tid + it * 256;
        int r = idx >> 5;
        int c4 = (idx & 31) * 4;
        int gc = col0 + c4;
        if (gc >= NCOLS) continue;
        int n = row0 + r;
        float4 v = *(float4*)&stage[r][c4];
        int b = gc / DD;
        int cc = gc - b * DD;
        if (b == 0) {
            *(float4*)&d_Sf[(size_t)n * SFST + cc] = v;
        } else if (b == 4) {
            *(float4*)&d_Sf[(size_t)n * SFST + 304 + cc] = v;
        } else if (b == 3) {
            if (n < Nn) *(float4*)&out[(size_t)n * DD + cc] = v;
        } else {
            int off = (b == 1) ? 0 : (b == 2 ? 320 : 640);   // K, V, Cs
            __half2 h0 = __floats2half2_rn(v.x, v.y);
            __half2 h1 = __floats2half2_rn(v.z, v.w);
            uint2 u = make_uint2(*(uint32_t*)&h0, *(uint32_t*)&h1);
            *(uint2*)&d_Sh[(size_t)n * SHST + off + cc] = u;
        }
    }
}

// ---------------- CSR build ----------------
__global__ void zerodeg_kernel(int Nn) {
    int i = blockIdx.x * blockDim.x + threadIdx.x;
    if (i < Nn) d_deg[i] = 0;
}
__global__ void hist_kernel(const int* __restrict__ EI, int Ee) {
    int e = blockIdx.x * blockDim.x + threadIdx.x;
    if (e < Ee) atomicAdd(&d_deg[EI[Ee + e]], 1);
}
__global__ void scan1_kernel(int Nn) {
    __shared__ int sdata[256];
    int t = threadIdx.x;
    int i = blockIdx.x * 256 + t;
    int v = (i < Nn) ? d_deg[i] : 0;
    sdata[t] = v;
    __syncthreads();
    #pragma unroll
    for (int off = 1; off < 256; off <<= 1) {
        int x = (t >= off) ? sdata[t - off] : 0;
        __syncthreads();
        sdata[t] += x;
        __syncthreads();
    }
    if (i < Nn) d_rowptr[i] = sdata[t] - v;
    if (t == 255) d_blksum[blockIdx.x] = sdata[255];
}
__global__ void scan2_kernel(int NB) {
    __shared__ int sdata[256];
    int t = threadIdx.x;
    int v = (t < NB) ? d_blksum[t] : 0;
    sdata[t] = v;
    __syncthreads();
    #pragma unroll
    for (int off = 1; off < 256; off <<= 1) {
        int x = (t >= off) ? sdata[t - off] : 0;
        __syncthreads();
        sdata[t] += x;
        __syncthreads();
    }
    if (t < NB) d_blksum[t] = sdata[t] - v;
}
__global__ void scan3_kernel(int Nn) {
    int i = blockIdx.x * blockDim.x + threadIdx.x;
    if (i >= Nn) return;
    int val = d_rowptr[i] + d_blksum[i >> 8];
    d_rowptr[i] = val;
    d_cursor[i] = val;
    if (i == Nn - 1) d_rowptr[Nn] = val + d_deg[i];
}
__global__ void scatter_kernel(const int* __restrict__ EI, int Ee) {
    int e = blockIdx.x * blockDim.x + threadIdx.x;
    if (e >= Ee) return;
    int dst = EI[Ee + e];
    int pos = atomicAdd(&d_cursor[dst], 1);
    d_edges[pos] = make_int2(EI[e], e);
}

// ---------------- fused edge kernel (QG/T algebraic form, single tree) ----------------
__global__ void __launch_bounds__(256) edgeF_kernel(const float* __restrict__ EA,
                                                    const float* __restrict__ Wcls,
                                                    const float* __restrict__ bcls,
                                                    float* __restrict__ out, int Nn) {
    __shared__ float sWcls8[DD * 8];      // padded rows: [c][0..4]=Wcls, [5..7]=0
    __shared__ float2 sW2i[DD];           // (W2a, W2b) interleaved
    __shared__ float sG[8 * DD];
    __shared__ float sBcls[5];
    for (int i = threadIdx.x; i < DD * 8; i += 256) {
        int c = i >> 3, k = i & 7;
        sWcls8[i] = (k < 5) ? Wcls[c * 5 + k] : 0.0f;
    }
    for (int i = threadIdx.x; i < DD; i += 256)
        sW2i[i] = make_float2(d_W2f[i], d_W2f[DD + i]);
    for (int i = threadIdx.x; i < 8 * DD; i += 256) sG[i] = d_G8[i];
    if (threadIdx.x < 5) sBcls[threadIdx.x] = bcls[threadIdx.x];
    __syncthreads();

    const uint32_t FULL = 0xffffffffu;
    int lane = threadIdx.x & 31;
    int n = blockIdx.x * 8 + (threadIdx.x >> 5);
    if (n >= Nn) return;                     // uniform per warp

    int beg = d_rowptr[n], end = d_rowptr[n + 1];
    const float* rowQ = d_Sf + (size_t)n * SFST;

    // lane ownership: head oh = lane>>3, class oj = lane&7
    int oh = lane >> 3, oj = lane & 7;

    // per-node QG[oh][oj] = sum over head oh's 75 cols of q_c * G[oj][c]
    float QG = 0.0f;
    {
        const float* qb = rowQ + oh * 75;
        const float* gb = sG + oj * DD + oh * 75;
        #pragma unroll 5
        for (int c = 0; c < 75; c++) QG = fmaf(__ldg(&qb[c]), gb[c], QG);
    }

    float4 q[3], cd[3], accv[3];
    #pragma unroll
    for (int j = 0; j < 3; j++) {
        int ch = lane + 32 * j;
        if (ch < 75) {
            q[j]  = __ldg((const float4*)&rowQ[4 * ch]);
            cd[j] = __ldg((const float4*)&rowQ[304 + 4 * ch]);
        } else {
            q[j] = make_float4(0, 0, 0, 0);
            cd[j] = make_float4(0, 0, 0, 0);
        }
        accv[j] = make_float4(0, 0, 0, 0);
    }
    float Tacc = 0.0f;    // T[oh][oj] accumulator (j=7 column doubles as den_h)
    const float sc = 0.115470053837925152f;  // 1/sqrt(75)

    for (int p = beg; p < end; p++) {
        int2 se = __ldg(&d_edges[p]);
        const __half* rowS = d_Sh + (size_t)se.x * SHST;
        float4 ea = __ldg((const float4*)&EA[4 * se.y]);

        uint2 ku[3], vu[3], csu[3];
        #pragma unroll
        for (int j = 0; j < 3; j++) {
            int ch = lane + 32 * j;
            if (ch < 75) {
                ku[j]  = __ldg((const uint2*)(rowS + 4 * ch));
                vu[j]  = __ldg((const uint2*)(rowS + 320 + 4 * ch));
                csu[j] = __ldg((const uint2*)(rowS + 640 + 4 * ch));
            } else {
                ku[j] = make_uint2(0, 0); vu[j] = make_uint2(0, 0); csu[j] = make_uint2(0, 0);
            }
        }

        float l0 = 0, l1 = 0, l2 = 0, l3 = 0, l4 = 0;
        float a0 = 0, a1 = 0, a2 = 0, a3 = 0;
        #pragma unroll
        for (int j = 0; j < 3; j++) {
            int ch = lane + 32 * j;
            if (ch >= 75) continue;       // no shuffles inside; safe
            int c = 4 * ch;
            float4 cs4 = h4tof4(csu[j]);
            float4 k4  = h4tof4(ku[j]);
            #pragma unroll
            for (int i = 0; i < 4; i++) {
                int col = c + i;
                float2 w2 = sW2i[col];
                float h = fast_tanh((&cd[j].x)[i] + (&cs4.x)[i] + ea.z * w2.x + ea.w * w2.y);
                const float* wc = &sWcls8[col * 8];
                float4 wv4 = *(const float4*)wc;
                float wv5 = wc[4];
                l0 = fmaf(h, wv4.x, l0); l1 = fmaf(h, wv4.y, l1); l2 = fmaf(h, wv4.z, l2);
                l3 = fmaf(h, wv4.w, l3); l4 = fmaf(h, wv5, l4);
                float pr = (&q[j].x)[i] * (&k4.x)[i];
                if (col < 75) a0 += pr;
                else if (col < 150) a1 += pr;
                else if (col < 225) a2 += pr;
                else a3 += pr;
            }
        }

        // single 9-value tree
        #pragma unroll
        for (int o = 16; o; o >>= 1) {
            l0 += __shfl_xor_sync(FULL, l0, o);
            l1 += __shfl_xor_sync(FULL, l1, o);
            l2 += __shfl_xor_sync(FULL, l2, o);
            l3 += __shfl_xor_sync(FULL, l3, o);
            l4 += __shfl_xor_sync(FULL, l4, o);
            a0 += __shfl_xor_sync(FULL, a0, o);
            a1 += __shfl_xor_sync(FULL, a1, o);
            a2 += __shfl_xor_sync(FULL, a2, o);
            a3 += __shfl_xor_sync(FULL, a3, o);
        }
        l0 += sBcls[0]; l1 += sBcls[1]; l2 += sBcls[2]; l3 += sBcls[3]; l4 += sBcls[4];
        float m = fmaxf(fmaxf(fmaxf(l0, l1), fmaxf(l2, l3)), l4);
        float p0 = __expf(l0 - m), p1 = __expf(l1 - m), p2 = __expf(l2 - m);
        float p3 = __expf(l3 - m), p4 = __expf(l4 - m);
        float inv = 1.0f / (p0 + p1 + p2 + p3 + p4);
        p0 *= inv; p1 *= inv; p2 *= inv; p3 *= inv; p4 *= inv;
        float t0 = ea.x > 0.0f ? 1.0f : 0.0f;
        float t1 = ea.y < 0.0f ? 1.0f : 0.0f;

        // lane-owned p8[oj]
        float pj = (oj == 0) ? p0 : (oj == 1) ? p1 : (oj == 2) ? p2 : (oj == 3) ? p3
                  : (oj == 4) ? p4 : (oj == 5) ? t0 : (oj == 6) ? t1 : 1.0f;

        // q.ef for own head: segmented width-8 reduce of pj*QG
        float qef = pj * QG;
        qef += __shfl_xor_sync(FULL, qef, 1, 8);
        qef += __shfl_xor_sync(FULL, qef, 2, 8);
        qef += __shfl_xor_sync(FULL, qef, 4, 8);

        float ah = (oh == 0) ? a0 : (oh == 1) ? a1 : (oh == 2) ? a2 : a3;
        float wv = __expf((ah + qef) * sc);     // w for own head

        // broadcast per-head weights
        float w0 = __shfl_sync(FULL, wv, 0);
        float w1 = __shfl_sync(FULL, wv, 8);
        float w2h = __shfl_sync(FULL, wv, 16);
        float w3h = __shfl_sync(FULL, wv, 24);

        Tacc = fmaf(wv, pj, Tacc);              // T[oh][oj] += w_h * p8_j

        #pragma unroll
        for (int j = 0; j < 3; j++) {
            int ch = lane + 32 * j;
            if (ch >= 75) continue;
            int c = 4 * ch;
            float4 v4 = h4tof4(vu[j]);
            #pragma unroll
            for (int i = 0; i < 4; i++) {
                int col = c + i;
                float w = col < 75 ? w0 : (col < 150 ? w1 : (col < 225 ? w2h : w3h));
                (&accv[j].x)[i] = fmaf(w, (&v4.x)[i], (&accv[j].x)[i]);
            }
        }
    }

    // ---- epilogue: out_c = skip + (accv_c + sum_j T[h][j] G[j][c]) / den_h ----
    // all lanes execute all shuffles (valid flag gates only loads/stores)
    #pragma unroll
    for (int j = 0; j < 3; j++) {
        int ch = lane + 32 * j;
        bool valid = (ch < 75);
        int c = valid ? 4 * ch : 0;
        float4 o4 = make_float4(0, 0, 0, 0);
        if (valid) o4 = *(float4*)&out[(size_t)n * DD + c];
        #pragma unroll
        for (int i = 0; i < 4; i++) {
            int col = c + i;
            int h = col < 75 ? 0 : (col < 150 ? 1 : (col < 225 ? 2 : 3));
            int base = h * 8;
            float add = (&accv[j].x)[i];
            float den = 0.0f;
            #pragma unroll
            for (int jj = 0; jj < 8; jj++) {
                float tv = __shfl_sync(FULL, Tacc, base + jj);
                add = fmaf(tv, sG[jj * DD + col], add);
                if (jj == 7) den = tv;
            }
            float invd = den > 0.0f ? __fdividef(1.0f, den) : 0.0f;
            (&o4.x)[i] = fmaf(add, invd, (&o4.x)[i]);
        }
        if (valid) *(float4*)&out[(size_t)n * DD + c] = o4;
    }
}

// ---------------- host launcher ----------------
extern "C" void kernel_launch(void* const* d_in, const int* in_sizes, int n_in,
                              void* d_out, int out_size) {
    const float* x     = (const float*)d_in[0];
    const int*   EI    = (const int*)d_in[1];
    const float* EA    = (const float*)d_in[2];
    const float* nrm   = (const float*)d_in[3];
    const float* Wq    = (const float*)d_in[4];
    const float* bq    = (const float*)d_in[5];
    const float* Wk    = (const float*)d_in[6];
    const float* bk    = (const float*)d_in[7];
    const float* Wv    = (const float*)d_in[8];
    const float* bv    = (const float*)d_in[9];
    const float* We    = (const float*)d_in[10];
    const float* Wn    = (const float*)d_in[11];
    const float* bn    = (const float*)d_in[12];
    const float* Wxy   = (const float*)d_in[13];
    const float* bxy   = (const float*)d_in[14];
    const float* Wloc  = (const float*)d_in[15];
    const float* bloc  = (const float*)d_in[16];
    const float* Wobj  = (const float*)d_in[17];
    const float* bobj  = (const float*)d_in[18];
    const float* Wfus  = (const float*)d_in[19];
    const float* bfus  = (const float*)d_in[20];
    const float* Wcls  = (const float*)d_in[21];
    const float* bcls  = (const float*)d_in[22];
    const float* Wskip = (const float*)d_in[23];
    const float* bskip = (const float*)d_in[24];
    const float* vocab = (const float*)d_in[25];

    int Nn = in_sizes[0] / DD;
    int Ee = in_sizes[1] / 2;
    float* out = (float*)d_out;

    static bool attr_set = false;
    const int gemm_smem = STAGES * (128 * 40 + 128 * 40) * 2;   // 81920 B
    if (!attr_set) {
        cudaFuncSetAttribute(gemm_fp16_kernel, cudaFuncAttributeMaxDynamicSharedMemorySize, gemm_smem);
        attr_set = true;
    }

    fold1_kernel<<<(DD + 127) / 128, 128>>>(Wn, Wxy, Wloc, Wfus, vocab, bxy, bn, bobj, bloc, bfus);
    fold2_kernel<<<(DD + 127) / 128, 128>>>(We);
    buildA_kernel<<<(Nn * 304 + 255) / 256, 256>>>(x, nrm, Nn);
    buildW_kernel<<<(NCOLS * 304 + 255) / 256, 256>>>(Wq, Wk, Wv, Wskip, Wobj, bq, bk, bv, bskip);

    dim3 gg(15, MPAD / 128);
    gemm_fp16_kernel<<<gg, 256, gemm_smem>>>(out, Nn);

    int NB = (Nn + 255) / 256;
    zerodeg_kernel<<<NB, 256>>>(Nn);
    hist_kernel<<<(Ee + 255) / 256, 256>>>(EI, Ee);
    scan1_kernel<<<NB, 256>>>(Nn);
    scan2_kernel<<<1, 256>>>(NB);
    scan3_kernel<<<NB, 256>>>(Nn);
    scatter_kernel<<<(Ee + 255) / 256, 256>>>(EI, Ee);

    edgeF_kernel<<<(Nn + 7) / 8, 256>>>(EA, Wcls, bcls, out, Nn);
}

// round 11
// speedup vs baseline: 1.3617x; 1.3617x over previous
#include <cuda_runtime.h>
#include <cuda_fp16.h>
#include <mma.h>
#include <math.h>
#include <stdint.h>

using namespace nvcuda;

#define DD 300
#define NCOLS 1800
#define KK2 320             // K padded to 320 (zero-padded)
#define MAXN 50000
#define MAXE 250000
#define MPAD 50048          // 391 * 128
#define STAGES 4
#define KT 32
#define NT (KK2 / KT)       // 10
#define SFST 608            // d_Sf row stride (floats): Q[0..300), Cd[304..604)
#define SHST 960            // d_Sh row stride (halves): K[0..300), V[320..620), Cs[640..940)

// ---- static scratch (allocation-free rule: __device__ globals) ----
__device__ __half d_Ah[(size_t)MPAD * KK2];    // [MPAD][320] fp16, pads stay 0
__device__ __half d_WhT[(size_t)1920 * KK2];   // [1920][320] Wbig^T fp16
__device__ float  d_Sf[(size_t)MPAD * SFST];   // fp32: Q | Cd
__device__ __half d_Sh[(size_t)MPAD * SHST];   // fp16: K | V | Cs
__device__ float  d_NLi[3 * DD];
__device__ float  d_NLj[3 * DD];
__device__ float  d_W2f[2 * DD];
__device__ float  d_c0[DD];
__device__ float  d_T8[8 * DD];
__device__ float  d_G8[8 * DD];
// CSR scratch
__device__ int  d_deg[MAXN];
__device__ int  d_rowptr[MAXN + 1];
__device__ int  d_cursor[MAXN];
__device__ int  d_blksum[256];
__device__ int2 d_edges[MAXE];

__device__ __forceinline__ float fast_tanh(float x) {
    float r;
    asm("tanh.approx.f32 %0, %1;" : "=f"(r) : "f"(x));
    return r;
}

// ---------------- fold 1 ----------------
__global__ void fold1_kernel(const float* __restrict__ Wn, const float* __restrict__ Wxy,
                             const float* __restrict__ Wloc, const float* __restrict__ Wfus,
                             const float* __restrict__ vocab, const float* __restrict__ bxy,
                             const float* __restrict__ bn, const float* __restrict__ bobj,
                             const float* __restrict__ bloc, const float* __restrict__ bfus) {
    int c = blockIdx.x * blockDim.x + threadIdx.x;
    if (c >= DD) return;
    float nli0 = 0, nli1 = 0, nli2 = 0, nlj0 = 0, nlj1 = 0, nlj2 = 0;
    float w20 = 0, w21 = 0, c0 = 0;
    float t0 = 0, t1 = 0, t2 = 0, t3 = 0, t4 = 0, t5 = 0, t6 = 0;
    for (int k = 0; k < DD; k++) {
        float wl0 = Wloc[k * DD + c];
        float wl1 = Wloc[(DD + k) * DD + c];
        float wl2 = Wloc[(2 * DD + k) * DD + c];
        float wn0 = Wn[k], wn1 = Wn[DD + k], wn2 = Wn[2 * DD + k];
        nli0 = fmaf(wn0, wl1, nli0); nli1 = fmaf(wn1, wl1, nli1); nli2 = fmaf(wn2, wl1, nli2);
        nlj0 = fmaf(wn0, wl2, nlj0); nlj1 = fmaf(wn1, wl2, nlj1); nlj2 = fmaf(wn2, wl2, nlj2);
        w20 = fmaf(Wxy[k], wl0, w20); w21 = fmaf(Wxy[DD + k], wl0, w21);
        c0 = fmaf(bxy[k], wl0, c0);
        c0 = fmaf(bn[k], wl1 + wl2, c0);
        float wf0 = Wfus[k * DD + c];
        float wf1 = Wfus[(DD + k) * DD + c];
        t0 = fmaf(vocab[2 * DD + k], wf1, t0);
        t1 = fmaf(vocab[3 * DD + k], wf1, t1);
        t2 = fmaf(vocab[4 * DD + k], wf1, t2);
        t3 = fmaf(vocab[5 * DD + k], wf1, t3);
        t4 = fmaf(vocab[6 * DD + k], wf1, t4);
        t5 = fmaf(vocab[k], wf0, t5);
        t6 = fmaf(vocab[DD + k], wf0, t6);
    }
    d_NLi[0 * DD + c] = nli0; d_NLi[1 * DD + c] = nli1; d_NLi[2 * DD + c] = nli2;
    d_NLj[0 * DD + c] = nlj0; d_NLj[1 * DD + c] = nlj1; d_NLj[2 * DD + c] = nlj2;
    d_W2f[c] = w20; d_W2f[DD + c] = w21;
    d_c0[c] = c0 + bobj[c] + bloc[c];
    d_T8[0 * DD + c] = t0; d_T8[1 * DD + c] = t1; d_T8[2 * DD + c] = t2;
    d_T8[3 * DD + c] = t3; d_T8[4 * DD + c] = t4; d_T8[5 * DD + c] = t5;
    d_T8[6 * DD + c] = t6; d_T8[7 * DD + c] = bfus[c];
}

// ---------------- fold 2: G8 = T8 @ We ----------------
__global__ void fold2_kernel(const float* __restrict__ We) {
    int c = blockIdx.x * blockDim.x + threadIdx.x;
    if (c >= DD) return;
    float g[8] = {0, 0, 0, 0, 0, 0, 0, 0};
    for (int k = 0; k < DD; k++) {
        float w = We[k * DD + c];
        #pragma unroll
        for (int j = 0; j < 8; j++) g[j] = fmaf(d_T8[j * DD + k], w, g[j]);
    }
    #pragma unroll
    for (int j = 0; j < 8; j++) d_G8[j * DD + c] = g[j];
}

// ---------------- build A (fp16; pad entries never written, stay zero) ----------------
__global__ void buildA_kernel(const float* __restrict__ x, const float* __restrict__ nrm, int Nn) {
    int idx = blockIdx.x * blockDim.x + threadIdx.x;
    if (idx >= Nn * 304) return;
    int n = idx / 304, k = idx - n * 304;
    float v;
    if (k < DD) v = x[n * DD + k];
    else if (k < DD + 3) v = nrm[n * 3 + (k - DD)];
    else v = 1.0f;
    d_Ah[(size_t)n * KK2 + k] = __float2half_rn(v);
}

// ---------------- build WhT [c][k] fp16 ----------------
__global__ void buildW_kernel(const float* __restrict__ Wq, const float* __restrict__ Wk,
                              const float* __restrict__ Wv, const float* __restrict__ Wskip,
                              const float* __restrict__ Wobj, const float* __restrict__ bq,
                              const float* __restrict__ bk, const float* __restrict__ bv,
                              const float* __restrict__ bskip) {
    int idx = blockIdx.x * blockDim.x + threadIdx.x;
    if (idx >= NCOLS * 304) return;
    int c = idx / 304, k = idx - c * 304;
    int b = c / DD, cc = c - b * DD;
    float v = 0.0f;
    if (k < DD) {
        if (b == 0) v = Wq[k * DD + cc];
        else if (b == 1) v = Wk[k * DD + cc];
        else if (b == 2) v = Wv[k * DD + cc];
        else if (b == 3) v = Wskip[k * DD + cc];
        else if (b == 4) v = Wobj[k * DD + cc] - Wobj[(DD + k) * DD + cc];
        else v = Wobj[(DD + k) * DD + cc];
    } else if (k < DD + 3) {
        int r = k - DD;
        if (b == 4) v = d_NLi[r * DD + cc];
        else if (b == 5) v = d_NLj[r * DD + cc];
    } else {
        if (b == 0) v = bq[cc];
        else if (b == 1) v = bk[cc];
        else if (b == 2) v = bv[cc];
        else if (b == 3) v = bskip[cc];
        else if (b == 4) v = d_c0[cc];
    }
    d_WhT[(size_t)c * KK2 + k] = __float2half_rn(v);
}

// ---------------- node GEMM (fp16 wmma m16n16k16, cp.async 4-stage, routed epilogue) ----
__global__ void __launch_bounds__(256, 2) gemm_fp16_kernel(float* __restrict__ out, int Nn) {
    extern __shared__ __half sm[];
    __half (*As)[128][40] = (__half (*)[128][40])sm;
    __half (*Bs)[128][40] = (__half (*)[128][40])(sm + STAGES * 128 * 40);
    float (*stage)[132] = (float (*)[132])sm;

    int tid = threadIdx.x;
    int wid = tid >> 5;
    int wm = wid >> 2;
    int wn = wid & 3;
    int row0 = blockIdx.y * 128, col0 = blockIdx.x * 128;

    wmma::fragment<wmma::accumulator, 16, 16, 16, float> acc[4][2];
    #pragma unroll
    for (int i = 0; i < 4; i++)
        #pragma unroll
        for (int j = 0; j < 2; j++) wmma::fill_fragment(acc[i][j], 0.0f);

    auto loadStage = [&](int st, int kt) {
        #pragma unroll
        for (int u = 0; u < 2; u++) {
            int idx = tid + 256 * u;
            int row = idx >> 2, seg = idx & 3;
            const __half* ga = &d_Ah[(size_t)(row0 + row) * KK2 + kt + seg * 8];
            uint32_t da = (uint32_t)__cvta_generic_to_shared(&As[st][row][seg * 8]);
            asm volatile("cp.async.cg.shared.global [%0], [%1], 16;" :: "r"(da), "l"(ga));
            const __half* gb = &d_WhT[(size_t)(col0 + row) * KK2 + kt + seg * 8];
            uint32_t db = (uint32_t)__cvta_generic_to_shared(&Bs[st][row][seg * 8]);
            asm volatile("cp.async.cg.shared.global [%0], [%1], 16;" :: "r"(db), "l"(gb));
        }
    };

    #pragma unroll
    for (int i = 0; i < STAGES - 1; i++) {
        loadStage(i, i * KT);
        asm volatile("cp.async.commit_group;");
    }

    for (int s = 0; s < NT; s++) {
        asm volatile("cp.async.wait_group %0;" :: "n"(STAGES - 2));
        __syncthreads();
        int ld = s + STAGES - 1;
        if (ld < NT) loadStage(ld & (STAGES - 1), ld * KT);
        asm volatile("cp.async.commit_group;");

        int st = s & (STAGES - 1);
        #pragma unroll
        for (int ks = 0; ks < 2; ks++) {
            int k0 = ks * 16;
            wmma::fragment<wmma::matrix_b, 16, 16, 16, __half, wmma::col_major> bf[2];
            #pragma unroll
            for (int j = 0; j < 2; j++)
                wmma::load_matrix_sync(bf[j], &Bs[st][wn * 32 + j * 16][k0], 40);
            #pragma unroll
            for (int i = 0; i < 4; i++) {
                wmma::fragment<wmma::matrix_a, 16, 16, 16, __half, wmma::row_major> af;
                wmma::load_matrix_sync(af, &As[st][wm * 64 + i * 16][k0], 40);
                #pragma unroll
                for (int j = 0; j < 2; j++)
                    wmma::mma_sync(acc[i][j], af, bf[j], acc[i][j]);
            }
        }
    }

    asm volatile("cp.async.wait_group 0;");
    __syncthreads();
    #pragma unroll
    for (int i = 0; i < 4; i++)
        #pragma unroll
        for (int j = 0; j < 2; j++)
            wmma::store_matrix_sync(&stage[wm * 64 + i * 16][wn * 32 + j * 16],
                                    acc[i][j], 132, wmma::mem_row_major);
    __syncthreads();

    #pragma unroll
    for (int it = 0; it < 16; it++) {
        int idx = tid + it * 256;
        int r = idx >> 5;
        int c4 = (idx & 31) * 4;
        int gc = col0 + c4;
        if (gc >= NCOLS) continue;
        int n = row0 + r;
        float4 v = *(float4*)&stage[r][c4];
        int b = gc / DD;
        int cc = gc - b * DD;
        if (b == 0) {
            *(float4*)&d_Sf[(size_t)n * SFST + cc] = v;
        } else if (b == 4) {
            *(float4*)&d_Sf[(size_t)n * SFST + 304 + cc] = v;
        } else if (b == 3) {
            if (n < Nn) *(float4*)&out[(size_t)n * DD + cc] = v;
        } else {
            int off = (b == 1) ? 0 : (b == 2 ? 320 : 640);   // K, V, Cs
            __half2 h0 = __floats2half2_rn(v.x, v.y);
            __half2 h1 = __floats2half2_rn(v.z, v.w);
            uint2 u = make_uint2(*(uint32_t*)&h0, *(uint32_t*)&h1);
            *(uint2*)&d_Sh[(size_t)n * SHST + off + cc] = u;
        }
    }
}

// ---------------- CSR build ----------------
__global__ void zerodeg_kernel(int Nn) {
    int i = blockIdx.x * blockDim.x + threadIdx.x;
    if (i < Nn) d_deg[i] = 0;
}
__global__ void hist_kernel(const int* __restrict__ EI, int Ee) {
    int e = blockIdx.x * blockDim.x + threadIdx.x;
    if (e < Ee) atomicAdd(&d_deg[EI[Ee + e]], 1);
}
__global__ void scan1_kernel(int Nn) {
    __shared__ int sdata[256];
    int t = threadIdx.x;
    int i = blockIdx.x * 256 + t;
    int v = (i < Nn) ? d_deg[i] : 0;
    sdata[t] = v;
    __syncthreads();
    #pragma unroll
    for (int off = 1; off < 256; off <<= 1) {
        int x = (t >= off) ? sdata[t - off] : 0;
        __syncthreads();
        sdata[t] += x;
        __syncthreads();
    }
    if (i < Nn) d_rowptr[i] = sdata[t] - v;
    if (t == 255) d_blksum[blockIdx.x] = sdata[255];
}
__global__ void scan2_kernel(int NB) {
    __shared__ int sdata[256];
    int t = threadIdx.x;
    int v = (t < NB) ? d_blksum[t] : 0;
    sdata[t] = v;
    __syncthreads();
    #pragma unroll
    for (int off = 1; off < 256; off <<= 1) {
        int x = (t >= off) ? sdata[t - off] : 0;
        __syncthreads();
        sdata[t] += x;
        __syncthreads();
    }
    if (t < NB) d_blksum[t] = sdata[t] - v;
}
__global__ void scan3_kernel(int Nn) {
    int i = blockIdx.x * blockDim.x + threadIdx.x;
    if (i >= Nn) return;
    int val = d_rowptr[i] + d_blksum[i >> 8];
    d_rowptr[i] = val;
    d_cursor[i] = val;
    if (i == Nn - 1) d_rowptr[Nn] = val + d_deg[i];
}
__global__ void scatter_kernel(const int* __restrict__ EI, int Ee) {
    int e = blockIdx.x * blockDim.x + threadIdx.x;
    if (e >= Ee) return;
    int dst = EI[Ee + e];
    int pos = atomicAdd(&d_cursor[dst], 1);
    d_edges[pos] = make_int2(EI[e], e);
}

// ---------------- fused edge kernel v3: stride-32 ownership, conflict-free smem ----------
__global__ void __launch_bounds__(256) edgeF_kernel(const float* __restrict__ EA,
                                                    const float* __restrict__ Wcls,
                                                    const float* __restrict__ bcls,
                                                    float* __restrict__ out, int Nn) {
    __shared__ float sWc[5 * DD];         // [k][c] transposed
    __shared__ float sG[8 * DD];          // [j][c]
    __shared__ float2 sW2[DD];            // (W2a, W2b)
    __shared__ float sBcls[5];
    for (int i = threadIdx.x; i < 5 * DD; i += 256) {
        int k = i / DD, c = i - k * DD;
        sWc[i] = Wcls[c * 5 + k];
    }
    for (int i = threadIdx.x; i < 8 * DD; i += 256) sG[i] = d_G8[i];
    for (int i = threadIdx.x; i < DD; i += 256)
        sW2[i] = make_float2(d_W2f[i], d_W2f[DD + i]);
    if (threadIdx.x < 5) sBcls[threadIdx.x] = bcls[threadIdx.x];
    __syncthreads();

    const uint32_t FULL = 0xffffffffu;
    int lane = threadIdx.x & 31;
    int n = blockIdx.x * 8 + (threadIdx.x >> 5);
    if (n >= Nn) return;                  // uniform per warp

    int beg = d_rowptr[n], end = d_rowptr[n + 1];
    const float* rowQ = d_Sf + (size_t)n * SFST;

    int oh = lane >> 3, oj = lane & 7;
    // QG[oh][oj] = sum_{c in head oh} q_c * G[oj][c]
    float QG = 0.0f;
    {
        const float* qb = rowQ + oh * 75;
        const float* gb = sG + oj * DD + oh * 75;
        #pragma unroll 5
        for (int c = 0; c < 75; c++) QG = fmaf(__ldg(&qb[c]), gb[c], QG);
    }

    // stride-32 ownership: slot s -> col = lane + 32*s (s=0..9; s=9 valid iff lane<12)
    float q[10], cd[10], accv[10];
    #pragma unroll
    for (int s = 0; s < 10; s++) {
        int col = lane + 32 * s;
        bool valid = col < DD;
        q[s]  = valid ? __ldg(&rowQ[col]) : 0.0f;
        cd[s] = valid ? __ldg(&rowQ[304 + col]) : 0.0f;
        accv[s] = 0.0f;
    }
    float Tacc = 0.0f;
    const float sc = 0.115470053837925152f;  // 1/sqrt(75)

    for (int p = beg; p < end; p++) {
        int2 se = __ldg(&d_edges[p]);
        const __half* rowS = d_Sh + (size_t)se.x * SHST;
        float4 ea = __ldg((const float4*)&EA[4 * se.y]);

        float vv[10];
        float l0 = 0, l1 = 0, l2 = 0, l3 = 0, l4 = 0;
        float a0 = 0, a1 = 0, a2 = 0, a3 = 0;
        #pragma unroll
        for (int s = 0; s < 10; s++) {
            int col = lane + 32 * s;
            if (col < DD) {
                float kk = __half2float(__ldg(rowS + col));
                vv[s]    = __half2float(__ldg(rowS + 320 + col));
                float cs = __half2float(__ldg(rowS + 640 + col));
                float2 w2 = sW2[col];
                float h = fast_tanh(cd[s] + cs + ea.z * w2.x + ea.w * w2.y);
                l0 = fmaf(h, sWc[col], l0);
                l1 = fmaf(h, sWc[DD + col], l1);
                l2 = fmaf(h, sWc[2 * DD + col], l2);
                l3 = fmaf(h, sWc[3 * DD + col], l3);
                l4 = fmaf(h, sWc[4 * DD + col], l4);
                float pr = q[s] * kk;
                if (col < 75) a0 += pr;
                else if (col < 150) a1 += pr;
                else if (col < 225) a2 += pr;
                else a3 += pr;
            } else {
                vv[s] = 0.0f;
            }
        }

        // single 9-value tree (no shuffles above; all lanes here)
        #pragma unroll
        for (int o = 16; o; o >>= 1) {
            l0 += __shfl_xor_sync(FULL, l0, o);
            l1 += __shfl_xor_sync(FULL, l1, o);
            l2 += __shfl_xor_sync(FULL, l2, o);
            l3 += __shfl_xor_sync(FULL, l3, o);
            l4 += __shfl_xor_sync(FULL, l4, o);
            a0 += __shfl_xor_sync(FULL, a0, o);
            a1 += __shfl_xor_sync(FULL, a1, o);
            a2 += __shfl_xor_sync(FULL, a2, o);
            a3 += __shfl_xor_sync(FULL, a3, o);
        }
        l0 += sBcls[0]; l1 += sBcls[1]; l2 += sBcls[2]; l3 += sBcls[3]; l4 += sBcls[4];
        float m = fmaxf(fmaxf(fmaxf(l0, l1), fmaxf(l2, l3)), l4);
        float p0 = __expf(l0 - m), p1 = __expf(l1 - m), p2 = __expf(l2 - m);
        float p3 = __expf(l3 - m), p4 = __expf(l4 - m);
        float inv = 1.0f / (p0 + p1 + p2 + p3 + p4);
        p0 *= inv; p1 *= inv; p2 *= inv; p3 *= inv; p4 *= inv;
        float t0 = ea.x > 0.0f ? 1.0f : 0.0f;
        float t1 = ea.y < 0.0f ? 1.0f : 0.0f;

        float pj = (oj == 0) ? p0 : (oj == 1) ? p1 : (oj == 2) ? p2 : (oj == 3) ? p3
                  : (oj == 4) ? p4 : (oj == 5) ? t0 : (oj == 6) ? t1 : 1.0f;

        float qef = pj * QG;
        qef += __shfl_xor_sync(FULL, qef, 1, 8);
        qef += __shfl_xor_sync(FULL, qef, 2, 8);
        qef += __shfl_xor_sync(FULL, qef, 4, 8);

        float ah = (oh == 0) ? a0 : (oh == 1) ? a1 : (oh == 2) ? a2 : a3;
        float wv = __expf((ah + qef) * sc);

        float w0 = __shfl_sync(FULL, wv, 0);
        float w1 = __shfl_sync(FULL, wv, 8);
        float w2h = __shfl_sync(FULL, wv, 16);
        float w3h = __shfl_sync(FULL, wv, 24);

        Tacc = fmaf(wv, pj, Tacc);

        #pragma unroll
        for (int s = 0; s < 10; s++) {
            int col = lane + 32 * s;
            if (col < DD) {
                float w = col < 75 ? w0 : (col < 150 ? w1 : (col < 225 ? w2h : w3h));
                accv[s] = fmaf(w, vv[s], accv[s]);
            }
        }
    }

    // epilogue: out_c += (accv_c + sum_j T[h][j]*G[j][c]) / T[h][7]
    #pragma unroll
    for (int s = 0; s < 10; s++) {
        int col = lane + 32 * s;
        bool valid = col < DD;
        int cc = valid ? col : 0;
        int h = cc < 75 ? 0 : (cc < 150 ? 1 : (cc < 225 ? 2 : 3));
        int base = h * 8;
        float add = accv[s];
        float den = 0.0f;
        #pragma unroll
        for (int jj = 0; jj < 8; jj++) {
            float tv = __shfl_sync(FULL, Tacc, base + jj);
            add = fmaf(tv, sG[jj * DD + cc], add);
            if (jj == 7) den = tv;
        }
        if (valid) {
            float invd = den > 0.0f ? __fdividef(1.0f, den) : 0.0f;
            out[(size_t)n * DD + col] += add * invd;
        }
    }
}

// ---------------- host launcher ----------------
extern "C" void kernel_launch(void* const* d_in, const int* in_sizes, int n_in,
                              void* d_out, int out_size) {
    const float* x     = (const float*)d_in[0];
    const int*   EI    = (const int*)d_in[1];
    const float* EA    = (const float*)d_in[2];
    const float* nrm   = (const float*)d_in[3];
    const float* Wq    = (const float*)d_in[4];
    const float* bq    = (const float*)d_in[5];
    const float* Wk    = (const float*)d_in[6];
    const float* bk    = (const float*)d_in[7];
    const float* Wv    = (const float*)d_in[8];
    const float* bv    = (const float*)d_in[9];
    const float* We    = (const float*)d_in[10];
    const float* Wn    = (const float*)d_in[11];
    const float* bn    = (const float*)d_in[12];
    const float* Wxy   = (const float*)d_in[13];
    const float* bxy   = (const float*)d_in[14];
    const float* Wloc  = (const float*)d_in[15];
    const float* bloc  = (const float*)d_in[16];
    const float* Wobj  = (const float*)d_in[17];
    const float* bobj  = (const float*)d_in[18];
    const float* Wfus  = (const float*)d_in[19];
    const float* bfus  = (const float*)d_in[20];
    const float* Wcls  = (const float*)d_in[21];
    const float* bcls  = (const float*)d_in[22];
    const float* Wskip = (const float*)d_in[23];
    const float* bskip = (const float*)d_in[24];
    const float* vocab = (const float*)d_in[25];

    int Nn = in_sizes[0] / DD;
    int Ee = in_sizes[1] / 2;
    float* out = (float*)d_out;

    static bool attr_set = false;
    const int gemm_smem = STAGES * (128 * 40 + 128 * 40) * 2;   // 81920 B
    if (!attr_set) {
        cudaFuncSetAttribute(gemm_fp16_kernel, cudaFuncAttributeMaxDynamicSharedMemorySize, gemm_smem);
        attr_set = true;
    }

    fold1_kernel<<<(DD + 127) / 128, 128>>>(Wn, Wxy, Wloc, Wfus, vocab, bxy, bn, bobj, bloc, bfus);
    fold2_kernel<<<(DD + 127) / 128, 128>>>(We);
    buildA_kernel<<<(Nn * 304 + 255) / 256, 256>>>(x, nrm, Nn);
    buildW_kernel<<<(NCOLS * 304 + 255) / 256, 256>>>(Wq, Wk, Wv, Wskip, Wobj, bq, bk, bv, bskip);

    dim3 gg(15, MPAD / 128);
    gemm_fp16_kernel<<<gg, 256, gemm_smem>>>(out, Nn);

    int NB = (Nn + 255) / 256;
    zerodeg_kernel<<<NB, 256>>>(Nn);
    hist_kernel<<<(Ee + 255) / 256, 256>>>(EI, Ee);
    scan1_kernel<<<NB, 256>>>(Nn);
    scan2_kernel<<<1, 256>>>(NB);
    scan3_kernel<<<NB, 256>>>(Nn);
    scatter_kernel<<<(Ee + 255) / 256, 256>>>(EI, Ee);

    edgeF_kernel<<<(Nn + 7) / 8, 256>>>(EA, Wcls, bcls, out, Nn);
}

// round 12
// speedup vs baseline: 2.5565x; 1.8775x over previous
#include <cuda_runtime.h>
#include <cuda_fp16.h>
#include <mma.h>
#include <math.h>
#include <stdint.h>

using namespace nvcuda;

#define DD 300
#define NCOLS 1800
#define KK2 320
#define MAXN 50000
#define MAXE 250000
#define MPAD 50048
#define STAGES 4
#define KT 32
#define NT (KK2 / KT)
#define SFST 608            // d_Sf: Q[0..300), Cd[304..604)
#define SHST 960            // d_Sh: K[0..300), V[320..620), Cs[640..940)

__device__ __half d_Ah[(size_t)MPAD * KK2];
__device__ __half d_WhT[(size_t)1920 * KK2];
__device__ float  d_Sf[(size_t)MPAD * SFST];
__device__ __half d_Sh[(size_t)MPAD * SHST];
__device__ float  d_NLi[3 * DD];
__device__ float  d_NLj[3 * DD];
__device__ float  d_W2f[2 * DD];
__device__ float  d_c0[DD];
__device__ float  d_T8[8 * DD];
__device__ float  d_G8[8 * DD];
__device__ int  d_deg[MAXN];
__device__ int  d_rowptr[MAXN + 1];
__device__ int  d_cursor[MAXN];
__device__ int  d_blksum[256];
__device__ int2 d_edges[MAXE];

__device__ __forceinline__ float fast_tanh(float x) {
    float r;
    asm("tanh.approx.f32 %0, %1;" : "=f"(r) : "f"(x));
    return r;
}

// ---------------- fold1b: block per output column c, k-parallel reduction ----------------
__global__ void __launch_bounds__(128) fold1b_kernel(
        const float* __restrict__ Wn, const float* __restrict__ Wxy,
        const float* __restrict__ Wloc, const float* __restrict__ Wfus,
        const float* __restrict__ vocab, const float* __restrict__ bxy,
        const float* __restrict__ bn, const float* __restrict__ bobj,
        const float* __restrict__ bloc, const float* __restrict__ bfus) {
    int c = blockIdx.x;
    int t = threadIdx.x;
    float pt[16];
    #pragma unroll
    for (int j = 0; j < 16; j++) pt[j] = 0.0f;

    for (int k = t; k < DD; k += 128) {
        float wl0 = Wloc[k * DD + c];
        float wl1 = Wloc[(DD + k) * DD + c];
        float wl2 = Wloc[(2 * DD + k) * DD + c];
        float wn0 = Wn[k], wn1 = Wn[DD + k], wn2 = Wn[2 * DD + k];
        pt[0] = fmaf(wn0, wl1, pt[0]); pt[1] = fmaf(wn1, wl1, pt[1]); pt[2] = fmaf(wn2, wl1, pt[2]);
        pt[3] = fmaf(wn0, wl2, pt[3]); pt[4] = fmaf(wn1, wl2, pt[4]); pt[5] = fmaf(wn2, wl2, pt[5]);
        pt[6] = fmaf(Wxy[k], wl0, pt[6]); pt[7] = fmaf(Wxy[DD + k], wl0, pt[7]);
        pt[8] = fmaf(bxy[k], wl0, pt[8]);
        pt[8] = fmaf(bn[k], wl1 + wl2, pt[8]);
        float wf0 = Wfus[k * DD + c];
        float wf1 = Wfus[(DD + k) * DD + c];
        pt[9]  = fmaf(vocab[2 * DD + k], wf1, pt[9]);
        pt[10] = fmaf(vocab[3 * DD + k], wf1, pt[10]);
        pt[11] = fmaf(vocab[4 * DD + k], wf1, pt[11]);
        pt[12] = fmaf(vocab[5 * DD + k], wf1, pt[12]);
        pt[13] = fmaf(vocab[6 * DD + k], wf1, pt[13]);
        pt[14] = fmaf(vocab[k], wf0, pt[14]);
        pt[15] = fmaf(vocab[DD + k], wf0, pt[15]);
    }

    __shared__ float sd[16][128];
    #pragma unroll
    for (int j = 0; j < 16; j++) sd[j][t] = pt[j];
    __syncthreads();
    #pragma unroll
    for (int off = 64; off; off >>= 1) {
        if (t < off) {
            #pragma unroll
            for (int j = 0; j < 16; j++) sd[j][t] += sd[j][t + off];
        }
        __syncthreads();
    }
    if (t == 0) {
        d_NLi[0 * DD + c] = sd[0][0]; d_NLi[1 * DD + c] = sd[1][0]; d_NLi[2 * DD + c] = sd[2][0];
        d_NLj[0 * DD + c] = sd[3][0]; d_NLj[1 * DD + c] = sd[4][0]; d_NLj[2 * DD + c] = sd[5][0];
        d_W2f[c] = sd[6][0]; d_W2f[DD + c] = sd[7][0];
        d_c0[c] = sd[8][0] + bobj[c] + bloc[c];
        d_T8[0 * DD + c] = sd[9][0];  d_T8[1 * DD + c] = sd[10][0];
        d_T8[2 * DD + c] = sd[11][0]; d_T8[3 * DD + c] = sd[12][0];
        d_T8[4 * DD + c] = sd[13][0]; d_T8[5 * DD + c] = sd[14][0];
        d_T8[6 * DD + c] = sd[15][0]; d_T8[7 * DD + c] = bfus[c];
    }
}

// ---------------- fold2b: block per c, k-parallel ----------------
__global__ void __launch_bounds__(64) fold2b_kernel(const float* __restrict__ We) {
    int c = blockIdx.x;
    int t = threadIdx.x;
    float g[8];
    #pragma unroll
    for (int j = 0; j < 8; j++) g[j] = 0.0f;
    for (int k = t; k < DD; k += 64) {
        float w = We[k * DD + c];
        #pragma unroll
        for (int j = 0; j < 8; j++) g[j] = fmaf(d_T8[j * DD + k], w, g[j]);
    }
    __shared__ float sd[8][64];
    #pragma unroll
    for (int j = 0; j < 8; j++) sd[j][t] = g[j];
    __syncthreads();
    #pragma unroll
    for (int off = 32; off; off >>= 1) {
        if (t < off) {
            #pragma unroll
            for (int j = 0; j < 8; j++) sd[j][t] += sd[j][t + off];
        }
        __syncthreads();
    }
    if (t == 0) {
        #pragma unroll
        for (int j = 0; j < 8; j++) d_G8[j * DD + c] = sd[j][0];
    }
}

// ---------------- build A ----------------
__global__ void buildA_kernel(const float* __restrict__ x, const float* __restrict__ nrm, int Nn) {
    int idx = blockIdx.x * blockDim.x + threadIdx.x;
    if (idx >= Nn * 304) return;
    int n = idx / 304, k = idx - n * 304;
    float v;
    if (k < DD) v = x[n * DD + k];
    else if (k < DD + 3) v = nrm[n * 3 + (k - DD)];
    else v = 1.0f;
    d_Ah[(size_t)n * KK2 + k] = __float2half_rn(v);
}

// ---------------- build WhT ----------------
__global__ void buildW_kernel(const float* __restrict__ Wq, const float* __restrict__ Wk,
                              const float* __restrict__ Wv, const float* __restrict__ Wskip,
                              const float* __restrict__ Wobj, const float* __restrict__ bq,
                              const float* __restrict__ bk, const float* __restrict__ bv,
                              const float* __restrict__ bskip) {
    int idx = blockIdx.x * blockDim.x + threadIdx.x;
    if (idx >= NCOLS * 304) return;
    int c = idx / 304, k = idx - c * 304;
    int b = c / DD, cc = c - b * DD;
    float v = 0.0f;
    if (k < DD) {
        if (b == 0) v = Wq[k * DD + cc];
        else if (b == 1) v = Wk[k * DD + cc];
        else if (b == 2) v = Wv[k * DD + cc];
        else if (b == 3) v = Wskip[k * DD + cc];
        else if (b == 4) v = Wobj[k * DD + cc] - Wobj[(DD + k) * DD + cc];
        else v = Wobj[(DD + k) * DD + cc];
    } else if (k < DD + 3) {
        int r = k - DD;
        if (b == 4) v = d_NLi[r * DD + cc];
        else if (b == 5) v = d_NLj[r * DD + cc];
    } else {
        if (b == 0) v = bq[cc];
        else if (b == 1) v = bk[cc];
        else if (b == 2) v = bv[cc];
        else if (b == 3) v = bskip[cc];
        else if (b == 4) v = d_c0[cc];
    }
    d_WhT[(size_t)c * KK2 + k] = __float2half_rn(v);
}

// ---------------- node GEMM (unchanged from R8) ----------------
__global__ void __launch_bounds__(256, 2) gemm_fp16_kernel(float* __restrict__ out, int Nn) {
    extern __shared__ __half sm[];
    __half (*As)[128][40] = (__half (*)[128][40])sm;
    __half (*Bs)[128][40] = (__half (*)[128][40])(sm + STAGES * 128 * 40);
    float (*stage)[132] = (float (*)[132])sm;

    int tid = threadIdx.x;
    int wid = tid >> 5;
    int wm = wid >> 2;
    int wn = wid & 3;
    int row0 = blockIdx.y * 128, col0 = blockIdx.x * 128;

    wmma::fragment<wmma::accumulator, 16, 16, 16, float> acc[4][2];
    #pragma unroll
    for (int i = 0; i < 4; i++)
        #pragma unroll
        for (int j = 0; j < 2; j++) wmma::fill_fragment(acc[i][j], 0.0f);

    auto loadStage = [&](int st, int kt) {
        #pragma unroll
        for (int u = 0; u < 2; u++) {
            int idx = tid + 256 * u;
            int row = idx >> 2, seg = idx & 3;
            const __half* ga = &d_Ah[(size_t)(row0 + row) * KK2 + kt + seg * 8];
            uint32_t da = (uint32_t)__cvta_generic_to_shared(&As[st][row][seg * 8]);
            asm volatile("cp.async.cg.shared.global [%0], [%1], 16;" :: "r"(da), "l"(ga));
            const __half* gb = &d_WhT[(size_t)(col0 + row) * KK2 + kt + seg * 8];
            uint32_t db = (uint32_t)__cvta_generic_to_shared(&Bs[st][row][seg * 8]);
            asm volatile("cp.async.cg.shared.global [%0], [%1], 16;" :: "r"(db), "l"(gb));
        }
    };

    #pragma unroll
    for (int i = 0; i < STAGES - 1; i++) {
        loadStage(i, i * KT);
        asm volatile("cp.async.commit_group;");
    }

    for (int s = 0; s < NT; s++) {
        asm volatile("cp.async.wait_group %0;" :: "n"(STAGES - 2));
        __syncthreads();
        int ld = s + STAGES - 1;
        if (ld < NT) loadStage(ld & (STAGES - 1), ld * KT);
        asm volatile("cp.async.commit_group;");

        int st = s & (STAGES - 1);
        #pragma unroll
        for (int ks = 0; ks < 2; ks++) {
            int k0 = ks * 16;
            wmma::fragment<wmma::matrix_b, 16, 16, 16, __half, wmma::col_major> bf[2];
            #pragma unroll
            for (int j = 0; j < 2; j++)
                wmma::load_matrix_sync(bf[j], &Bs[st][wn * 32 + j * 16][k0], 40);
            #pragma unroll
            for (int i = 0; i < 4; i++) {
                wmma::fragment<wmma::matrix_a, 16, 16, 16, __half, wmma::row_major> af;
                wmma::load_matrix_sync(af, &As[st][wm * 64 + i * 16][k0], 40);
                #pragma unroll
                for (int j = 0; j < 2; j++)
                    wmma::mma_sync(acc[i][j], af, bf[j], acc[i][j]);
            }
        }
    }

    asm volatile("cp.async.wait_group 0;");
    __syncthreads();
    #pragma unroll
    for (int i = 0; i < 4; i++)
        #pragma unroll
        for (int j = 0; j < 2; j++)
            wmma::store_matrix_sync(&stage[wm * 64 + i * 16][wn * 32 + j * 16],
                                    acc[i][j], 132, wmma::mem_row_major);
    __syncthreads();

    #pragma unroll
    for (int it = 0; it < 16; it++) {
        int idx = tid + it * 256;
        int r = idx >> 5;
        int c4 = (idx & 31) * 4;
        int gc = col0 + c4;
        if (gc >= NCOLS) continue;
        int n = row0 + r;
        float4 v = *(float4*)&stage[r][c4];
        int b = gc / DD;
        int cc = gc - b * DD;
        if (b == 0) {
            *(float4*)&d_Sf[(size_t)n * SFST + cc] = v;
        } else if (b == 4) {
            *(float4*)&d_Sf[(size_t)n * SFST + 304 + cc] = v;
        } else if (b == 3) {
            if (n < Nn) *(float4*)&out[(size_t)n * DD + cc] = v;
        } else {
            int off = (b == 1) ? 0 : (b == 2 ? 320 : 640);
            __half2 h0 = __floats2half2_rn(v.x, v.y);
            __half2 h1 = __floats2half2_rn(v.z, v.w);
            uint2 u = make_uint2(*(uint32_t*)&h0, *(uint32_t*)&h1);
            *(uint2*)&d_Sh[(size_t)n * SHST + off + cc] = u;
        }
    }
}

// ---------------- CSR build ----------------
__global__ void zerodeg_kernel(int Nn) {
    int i = blockIdx.x * blockDim.x + threadIdx.x;
    if (i < Nn) d_deg[i] = 0;
}
__global__ void hist_kernel(const int* __restrict__ EI, int Ee) {
    int e = blockIdx.x * blockDim.x + threadIdx.x;
    if (e < Ee) atomicAdd(&d_deg[EI[Ee + e]], 1);
}
__global__ void scan1_kernel(int Nn) {
    __shared__ int sdata[256];
    int t = threadIdx.x;
    int i = blockIdx.x * 256 + t;
    int v = (i < Nn) ? d_deg[i] : 0;
    sdata[t] = v;
    __syncthreads();
    #pragma unroll
    for (int off = 1; off < 256; off <<= 1) {
        int x = (t >= off) ? sdata[t - off] : 0;
        __syncthreads();
        sdata[t] += x;
        __syncthreads();
    }
    if (i < Nn) d_rowptr[i] = sdata[t] - v;
    if (t == 255) d_blksum[blockIdx.x] = sdata[255];
}
__global__ void scan2_kernel(int NB) {
    __shared__ int sdata[256];
    int t = threadIdx.x;
    int v = (t < NB) ? d_blksum[t] : 0;
    sdata[t] = v;
    __syncthreads();
    #pragma unroll
    for (int off = 1; off < 256; off <<= 1) {
        int x = (t >= off) ? sdata[t - off] : 0;
        __syncthreads();
        sdata[t] += x;
        __syncthreads();
    }
    if (t < NB) d_blksum[t] = sdata[t] - v;
}
__global__ void scan3_kernel(int Nn) {
    int i = blockIdx.x * blockDim.x + threadIdx.x;
    if (i >= Nn) return;
    int val = d_rowptr[i] + d_blksum[i >> 8];
    d_rowptr[i] = val;
    d_cursor[i] = val;
    if (i == Nn - 1) d_rowptr[Nn] = val + d_deg[i];
}
__global__ void scatter_kernel(const int* __restrict__ EI, int Ee) {
    int e = blockIdx.x * blockDim.x + threadIdx.x;
    if (e >= Ee) return;
    int dst = EI[Ee + e];
    int pos = atomicAdd(&d_cursor[dst], 1);
    d_edges[pos] = make_int2(EI[e], e);
}

// ---------------- edgeF v4: hoisted half2 gathers, 128-thr blocks, grid-stride ----------
__global__ void __launch_bounds__(128, 5) edgeF_kernel(const float* __restrict__ EA,
                                                       const float* __restrict__ Wcls,
                                                       const float* __restrict__ bcls,
                                                       float* __restrict__ out, int Nn) {
    __shared__ float sWc[5 * DD];
    __shared__ float sG[8 * DD];
    __shared__ float2 sW2[DD];
    __shared__ float sBcls[5];
    for (int i = threadIdx.x; i < 5 * DD; i += 128) {
        int k = i / DD, c = i - k * DD;
        sWc[i] = Wcls[c * 5 + k];
    }
    for (int i = threadIdx.x; i < 8 * DD; i += 128) sG[i] = d_G8[i];
    for (int i = threadIdx.x; i < DD; i += 128)
        sW2[i] = make_float2(d_W2f[i], d_W2f[DD + i]);
    if (threadIdx.x < 5) sBcls[threadIdx.x] = bcls[threadIdx.x];
    __syncthreads();

    const uint32_t FULL = 0xffffffffu;
    int lane = threadIdx.x & 31;
    int warp = threadIdx.x >> 5;
    int oh = lane >> 3, oj = lane & 7;
    const float sc = 0.115470053837925152f;  // 1/sqrt(75)

    for (int n = blockIdx.x * 4 + warp; n < Nn; n += gridDim.x * 4) {
        int beg = d_rowptr[n], end = d_rowptr[n + 1];
        const float* rowQ = d_Sf + (size_t)n * SFST;

        // QG[oh][oj]
        float QG = 0.0f;
        {
            const float* qb = rowQ + oh * 75;
            const float* gb = sG + oj * DD + oh * 75;
            #pragma unroll 5
            for (int c = 0; c < 75; c++) QG = fmaf(__ldg(&qb[c]), gb[c], QG);
        }

        // pair ownership: slot s -> cols (2*lane + 64*s, +1); valid iff col0 < 300
        float2 q2[5], cd2[5], av[5];
        #pragma unroll
        for (int s = 0; s < 5; s++) {
            int col = 2 * lane + 64 * s;
            bool ok = col < DD;
            q2[s]  = ok ? *(const float2*)&rowQ[col] : make_float2(0, 0);
            cd2[s] = ok ? *(const float2*)&rowQ[304 + col] : make_float2(0, 0);
            av[s] = make_float2(0, 0);
        }
        float Tacc = 0.0f;

        for (int p = beg; p < end; p++) {
            int2 se = __ldg(&d_edges[p]);
            const __half* rowS = d_Sh + (size_t)se.x * SHST;
            float4 ea = __ldg((const float4*)&EA[4 * se.y]);

            // hoisted gathers: 15 half2 loads, MLP=15
            uint32_t kh[5], vh[5], ch[5];
            #pragma unroll
            for (int s = 0; s < 5; s++) {
                int col = 2 * lane + 64 * s;
                bool ok = col < DD;
                kh[s] = ok ? __ldg((const uint32_t*)(rowS + col)) : 0u;
                vh[s] = ok ? __ldg((const uint32_t*)(rowS + 320 + col)) : 0u;
                ch[s] = ok ? __ldg((const uint32_t*)(rowS + 640 + col)) : 0u;
            }

            float vf0[5], vf1[5];
            float l0 = 0, l1 = 0, l2 = 0, l3 = 0, l4 = 0;
            float a0 = 0, a1 = 0, a2 = 0, a3 = 0;
            #pragma unroll
            for (int s = 0; s < 5; s++) {
                int col = 2 * lane + 64 * s;
                float2 kf = __half22float2(*(__half2*)&kh[s]);
                float2 vf = __half22float2(*(__half2*)&vh[s]);
                float2 cf = __half22float2(*(__half2*)&ch[s]);
                vf0[s] = vf.x; vf1[s] = vf.y;
                if (col < DD) {
                    #pragma unroll
                    for (int i = 0; i < 2; i++) {
                        int c = col + i;
                        float2 w2 = sW2[c];
                        float cdv = i ? cd2[s].y : cd2[s].x;
                        float csv = i ? cf.y : cf.x;
                        float h = fast_tanh(cdv + csv + ea.z * w2.x + ea.w * w2.y);
                        l0 = fmaf(h, sWc[c], l0);
                        l1 = fmaf(h, sWc[DD + c], l1);
                        l2 = fmaf(h, sWc[2 * DD + c], l2);
                        l3 = fmaf(h, sWc[3 * DD + c], l3);
                        l4 = fmaf(h, sWc[4 * DD + c], l4);
                        float pr = (i ? q2[s].y : q2[s].x) * (i ? kf.y : kf.x);
                        if (c < 75) a0 += pr;
                        else if (c < 150) a1 += pr;
                        else if (c < 225) a2 += pr;
                        else a3 += pr;
                    }
                }
            }

            #pragma unroll
            for (int o = 16; o; o >>= 1) {
                l0 += __shfl_xor_sync(FULL, l0, o);
                l1 += __shfl_xor_sync(FULL, l1, o);
                l2 += __shfl_xor_sync(FULL, l2, o);
                l3 += __shfl_xor_sync(FULL, l3, o);
                l4 += __shfl_xor_sync(FULL, l4, o);
                a0 += __shfl_xor_sync(FULL, a0, o);
                a1 += __shfl_xor_sync(FULL, a1, o);
                a2 += __shfl_xor_sync(FULL, a2, o);
                a3 += __shfl_xor_sync(FULL, a3, o);
            }
            l0 += sBcls[0]; l1 += sBcls[1]; l2 += sBcls[2]; l3 += sBcls[3]; l4 += sBcls[4];
            float m = fmaxf(fmaxf(fmaxf(l0, l1), fmaxf(l2, l3)), l4);
            float p0 = __expf(l0 - m), p1 = __expf(l1 - m), p2 = __expf(l2 - m);
            float p3 = __expf(l3 - m), p4 = __expf(l4 - m);
            float inv = 1.0f / (p0 + p1 + p2 + p3 + p4);
            p0 *= inv; p1 *= inv; p2 *= inv; p3 *= inv; p4 *= inv;
            float t0 = ea.x > 0.0f ? 1.0f : 0.0f;
            float t1 = ea.y < 0.0f ? 1.0f : 0.0f;

            float pj = (oj == 0) ? p0 : (oj == 1) ? p1 : (oj == 2) ? p2 : (oj == 3) ? p3
                      : (oj == 4) ? p4 : (oj == 5) ? t0 : (oj == 6) ? t1 : 1.0f;

            float qef = pj * QG;
            qef += __shfl_xor_sync(FULL, qef, 1, 8);
            qef += __shfl_xor_sync(FULL, qef, 2, 8);
            qef += __shfl_xor_sync(FULL, qef, 4, 8);

            float ah = (oh == 0) ? a0 : (oh == 1) ? a1 : (oh == 2) ? a2 : a3;
            float wv = __expf((ah + qef) * sc);

            float w0 = __shfl_sync(FULL, wv, 0);
            float w1 = __shfl_sync(FULL, wv, 8);
            float w2h = __shfl_sync(FULL, wv, 16);
            float w3h = __shfl_sync(FULL, wv, 24);

            Tacc = fmaf(wv, pj, Tacc);

            #pragma unroll
            for (int s = 0; s < 5; s++) {
                int col = 2 * lane + 64 * s;
                if (col < DD) {
                    float wa = col < 75 ? w0 : (col < 150 ? w1 : (col < 225 ? w2h : w3h));
                    int c1 = col + 1;
                    float wb = c1 < 75 ? w0 : (c1 < 150 ? w1 : (c1 < 225 ? w2h : w3h));
                    av[s].x = fmaf(wa, vf0[s], av[s].x);
                    av[s].y = fmaf(wb, vf1[s], av[s].y);
                }
            }
        }

        // epilogue
        #pragma unroll
        for (int s = 0; s < 5; s++) {
            int col = 2 * lane + 64 * s;
            bool ok = col < DD;
            #pragma unroll
            for (int i = 0; i < 2; i++) {
                int cc = ok ? col + i : 0;
                int h = cc < 75 ? 0 : (cc < 150 ? 1 : (cc < 225 ? 2 : 3));
                int base = h * 8;
                float add = i ? av[s].y : av[s].x;
                float den = 0.0f;
                #pragma unroll
                for (int jj = 0; jj < 8; jj++) {
                    float tv = __shfl_sync(FULL, Tacc, base + jj);
                    add = fmaf(tv, sG[jj * DD + cc], add);
                    if (jj == 7) den = tv;
                }
                if (ok) {
                    float invd = den > 0.0f ? __fdividef(1.0f, den) : 0.0f;
                    out[(size_t)n * DD + cc] += add * invd;
                }
            }
        }
    }
}

// ---------------- host launcher ----------------
extern "C" void kernel_launch(void* const* d_in, const int* in_sizes, int n_in,
                              void* d_out, int out_size) {
    const float* x     = (const float*)d_in[0];
    const int*   EI    = (const int*)d_in[1];
    const float* EA    = (const float*)d_in[2];
    const float* nrm   = (const float*)d_in[3];
    const float* Wq    = (const float*)d_in[4];
    const float* bq    = (const float*)d_in[5];
    const float* Wk    = (const float*)d_in[6];
    const float* bk    = (const float*)d_in[7];
    const float* Wv    = (const float*)d_in[8];
    const float* bv    = (const float*)d_in[9];
    const float* We    = (const float*)d_in[10];
    const float* Wn    = (const float*)d_in[11];
    const float* bn    = (const float*)d_in[12];
    const float* Wxy   = (const float*)d_in[13];
    const float* bxy   = (const float*)d_in[14];
    const float* Wloc  = (const float*)d_in[15];
    const float* bloc  = (const float*)d_in[16];
    const float* Wobj  = (const float*)d_in[17];
    const float* bobj  = (const float*)d_in[18];
    const float* Wfus  = (const float*)d_in[19];
    const float* bfus  = (const float*)d_in[20];
    const float* Wcls  = (const float*)d_in[21];
    const float* bcls  = (const float*)d_in[22];
    const float* Wskip = (const float*)d_in[23];
    const float* bskip = (const float*)d_in[24];
    const float* vocab = (const float*)d_in[25];

    int Nn = in_sizes[0] / DD;
    int Ee = in_sizes[1] / 2;
    float* out = (float*)d_out;

    static bool attr_set = false;
    const int gemm_smem = STAGES * (128 * 40 + 128 * 40) * 2;   // 81920 B
    if (!attr_set) {
        cudaFuncSetAttribute(gemm_fp16_kernel, cudaFuncAttributeMaxDynamicSharedMemorySize, gemm_smem);
        attr_set = true;
    }

    fold1b_kernel<<<DD, 128>>>(Wn, Wxy, Wloc, Wfus, vocab, bxy, bn, bobj, bloc, bfus);
    fold2b_kernel<<<DD, 64>>>(We);
    buildA_kernel<<<(Nn * 304 + 255) / 256, 256>>>(x, nrm, Nn);
    buildW_kernel<<<(NCOLS * 304 + 255) / 256, 256>>>(Wq, Wk, Wv, Wskip, Wobj, bq, bk, bv, bskip);

    dim3 gg(15, MPAD / 128);
    gemm_fp16_kernel<<<gg, 256, gemm_smem>>>(out, Nn);

    int NB = (Nn + 255) / 256;
    zerodeg_kernel<<<NB, 256>>>(Nn);
    hist_kernel<<<(Ee + 255) / 256, 256>>>(EI, Ee);
    scan1_kernel<<<NB, 256>>>(Nn);
    scan2_kernel<<<1, 256>>>(NB);
    scan3_kernel<<<NB, 256>>>(Nn);
    scatter_kernel<<<(Ee + 255) / 256, 256>>>(EI, Ee);

    edgeF_kernel<<<1480, 128>>>(EA, Wcls, bcls, out, Nn);
}

// round 13
// speedup vs baseline: 2.6395x; 1.0325x over previous
#include <cuda_runtime.h>
#include <cuda_fp16.h>
#include <mma.h>
#include <math.h>
#include <stdint.h>

using namespace nvcuda;

#define DD 300
#define NCOLS 1800
#define KK2 320
#define MAXN 50000
#define MAXE 250000
#define MPAD 50048
#define STAGES 4
#define KT 32
#define NT (KK2 / KT)
#define SFST 608            // d_Sf (fp16): Q[0..300), Cd[304..604)
#define SHST 960            // d_Sh (fp16): K[0..300), V[320..620), Cs[640..940)

__device__ __half d_Ah[(size_t)MPAD * KK2];
__device__ __half d_WhT[(size_t)1920 * KK2];
__device__ __half d_Sf[(size_t)MPAD * SFST];   // fp16 now: Q | Cd
__device__ __half d_Sh[(size_t)MPAD * SHST];
__device__ float  d_NLi[3 * DD];
__device__ float  d_NLj[3 * DD];
__device__ float  d_W2f[2 * DD];
__device__ float  d_c0[DD];
__device__ float  d_T8[8 * DD];
__device__ float  d_G8[8 * DD];
__device__ int  d_deg[MAXN];
__device__ int  d_rowptr[MAXN + 1];
__device__ int  d_cursor[MAXN];
__device__ int  d_blksum[256];
__device__ int2 d_edges[MAXE];

__device__ __forceinline__ float fast_tanh(float x) {
    float r;
    asm("tanh.approx.f32 %0, %1;" : "=f"(r) : "f"(x));
    return r;
}

// ---------------- fold1b ----------------
__global__ void __launch_bounds__(128) fold1b_kernel(
        const float* __restrict__ Wn, const float* __restrict__ Wxy,
        const float* __restrict__ Wloc, const float* __restrict__ Wfus,
        const float* __restrict__ vocab, const float* __restrict__ bxy,
        const float* __restrict__ bn, const float* __restrict__ bobj,
        const float* __restrict__ bloc, const float* __restrict__ bfus) {
    int c = blockIdx.x;
    int t = threadIdx.x;
    float pt[16];
    #pragma unroll
    for (int j = 0; j < 16; j++) pt[j] = 0.0f;

    for (int k = t; k < DD; k += 128) {
        float wl0 = Wloc[k * DD + c];
        float wl1 = Wloc[(DD + k) * DD + c];
        float wl2 = Wloc[(2 * DD + k) * DD + c];
        float wn0 = Wn[k], wn1 = Wn[DD + k], wn2 = Wn[2 * DD + k];
        pt[0] = fmaf(wn0, wl1, pt[0]); pt[1] = fmaf(wn1, wl1, pt[1]); pt[2] = fmaf(wn2, wl1, pt[2]);
        pt[3] = fmaf(wn0, wl2, pt[3]); pt[4] = fmaf(wn1, wl2, pt[4]); pt[5] = fmaf(wn2, wl2, pt[5]);
        pt[6] = fmaf(Wxy[k], wl0, pt[6]); pt[7] = fmaf(Wxy[DD + k], wl0, pt[7]);
        pt[8] = fmaf(bxy[k], wl0, pt[8]);
        pt[8] = fmaf(bn[k], wl1 + wl2, pt[8]);
        float wf0 = Wfus[k * DD + c];
        float wf1 = Wfus[(DD + k) * DD + c];
        pt[9]  = fmaf(vocab[2 * DD + k], wf1, pt[9]);
        pt[10] = fmaf(vocab[3 * DD + k], wf1, pt[10]);
        pt[11] = fmaf(vocab[4 * DD + k], wf1, pt[11]);
        pt[12] = fmaf(vocab[5 * DD + k], wf1, pt[12]);
        pt[13] = fmaf(vocab[6 * DD + k], wf1, pt[13]);
        pt[14] = fmaf(vocab[k], wf0, pt[14]);
        pt[15] = fmaf(vocab[DD + k], wf0, pt[15]);
    }

    __shared__ float sd[16][128];
    #pragma unroll
    for (int j = 0; j < 16; j++) sd[j][t] = pt[j];
    __syncthreads();
    #pragma unroll
    for (int off = 64; off; off >>= 1) {
        if (t < off) {
            #pragma unroll
            for (int j = 0; j < 16; j++) sd[j][t] += sd[j][t + off];
        }
        __syncthreads();
    }
    if (t == 0) {
        d_NLi[0 * DD + c] = sd[0][0]; d_NLi[1 * DD + c] = sd[1][0]; d_NLi[2 * DD + c] = sd[2][0];
        d_NLj[0 * DD + c] = sd[3][0]; d_NLj[1 * DD + c] = sd[4][0]; d_NLj[2 * DD + c] = sd[5][0];
        d_W2f[c] = sd[6][0]; d_W2f[DD + c] = sd[7][0];
        d_c0[c] = sd[8][0] + bobj[c] + bloc[c];
        d_T8[0 * DD + c] = sd[9][0];  d_T8[1 * DD + c] = sd[10][0];
        d_T8[2 * DD + c] = sd[11][0]; d_T8[3 * DD + c] = sd[12][0];
        d_T8[4 * DD + c] = sd[13][0]; d_T8[5 * DD + c] = sd[14][0];
        d_T8[6 * DD + c] = sd[15][0]; d_T8[7 * DD + c] = bfus[c];
    }
}

// ---------------- fold2b ----------------
__global__ void __launch_bounds__(64) fold2b_kernel(const float* __restrict__ We) {
    int c = blockIdx.x;
    int t = threadIdx.x;
    float g[8];
    #pragma unroll
    for (int j = 0; j < 8; j++) g[j] = 0.0f;
    for (int k = t; k < DD; k += 64) {
        float w = We[k * DD + c];
        #pragma unroll
        for (int j = 0; j < 8; j++) g[j] = fmaf(d_T8[j * DD + k], w, g[j]);
    }
    __shared__ float sd[8][64];
    #pragma unroll
    for (int j = 0; j < 8; j++) sd[j][t] = g[j];
    __syncthreads();
    #pragma unroll
    for (int off = 32; off; off >>= 1) {
        if (t < off) {
            #pragma unroll
            for (int j = 0; j < 8; j++) sd[j][t] += sd[j][t + off];
        }
        __syncthreads();
    }
    if (t == 0) {
        #pragma unroll
        for (int j = 0; j < 8; j++) d_G8[j * DD + c] = sd[j][0];
    }
}

// ---------------- build A ----------------
__global__ void buildA_kernel(const float* __restrict__ x, const float* __restrict__ nrm, int Nn) {
    int idx = blockIdx.x * blockDim.x + threadIdx.x;
    if (idx >= Nn * 304) return;
    int n = idx / 304, k = idx - n * 304;
    float v;
    if (k < DD) v = x[n * DD + k];
    else if (k < DD + 3) v = nrm[n * 3 + (k - DD)];
    else v = 1.0f;
    d_Ah[(size_t)n * KK2 + k] = __float2half_rn(v);
}

// ---------------- build WhT ----------------
__global__ void buildW_kernel(const float* __restrict__ Wq, const float* __restrict__ Wk,
                              const float* __restrict__ Wv, const float* __restrict__ Wskip,
                              const float* __restrict__ Wobj, const float* __restrict__ bq,
                              const float* __restrict__ bk, const float* __restrict__ bv,
                              const float* __restrict__ bskip) {
    int idx = blockIdx.x * blockDim.x + threadIdx.x;
    if (idx >= NCOLS * 304) return;
    int c = idx / 304, k = idx - c * 304;
    int b = c / DD, cc = c - b * DD;
    float v = 0.0f;
    if (k < DD) {
        if (b == 0) v = Wq[k * DD + cc];
        else if (b == 1) v = Wk[k * DD + cc];
        else if (b == 2) v = Wv[k * DD + cc];
        else if (b == 3) v = Wskip[k * DD + cc];
        else if (b == 4) v = Wobj[k * DD + cc] - Wobj[(DD + k) * DD + cc];
        else v = Wobj[(DD + k) * DD + cc];
    } else if (k < DD + 3) {
        int r = k - DD;
        if (b == 4) v = d_NLi[r * DD + cc];
        else if (b == 5) v = d_NLj[r * DD + cc];
    } else {
        if (b == 0) v = bq[cc];
        else if (b == 1) v = bk[cc];
        else if (b == 2) v = bv[cc];
        else if (b == 3) v = bskip[cc];
        else if (b == 4) v = d_c0[cc];
    }
    d_WhT[(size_t)c * KK2 + k] = __float2half_rn(v);
}

// ---------------- node GEMM (fp16 epilogue for Q/Cd too) ----------------
__global__ void __launch_bounds__(256, 2) gemm_fp16_kernel(float* __restrict__ out, int Nn) {
    extern __shared__ __half sm[];
    __half (*As)[128][40] = (__half (*)[128][40])sm;
    __half (*Bs)[128][40] = (__half (*)[128][40])(sm + STAGES * 128 * 40);
    float (*stage)[132] = (float (*)[132])sm;

    int tid = threadIdx.x;
    int wid = tid >> 5;
    int wm = wid >> 2;
    int wn = wid & 3;
    int row0 = blockIdx.y * 128, col0 = blockIdx.x * 128;

    wmma::fragment<wmma::accumulator, 16, 16, 16, float> acc[4][2];
    #pragma unroll
    for (int i = 0; i < 4; i++)
        #pragma unroll
        for (int j = 0; j < 2; j++) wmma::fill_fragment(acc[i][j], 0.0f);

    auto loadStage = [&](int st, int kt) {
        #pragma unroll
        for (int u = 0; u < 2; u++) {
            int idx = tid + 256 * u;
            int row = idx >> 2, seg = idx & 3;
            const __half* ga = &d_Ah[(size_t)(row0 + row) * KK2 + kt + seg * 8];
            uint32_t da = (uint32_t)__cvta_generic_to_shared(&As[st][row][seg * 8]);
            asm volatile("cp.async.cg.shared.global [%0], [%1], 16;" :: "r"(da), "l"(ga));
            const __half* gb = &d_WhT[(size_t)(col0 + row) * KK2 + kt + seg * 8];
            uint32_t db = (uint32_t)__cvta_generic_to_shared(&Bs[st][row][seg * 8]);
            asm volatile("cp.async.cg.shared.global [%0], [%1], 16;" :: "r"(db), "l"(gb));
        }
    };

    #pragma unroll
    for (int i = 0; i < STAGES - 1; i++) {
        loadStage(i, i * KT);
        asm volatile("cp.async.commit_group;");
    }

    for (int s = 0; s < NT; s++) {
        asm volatile("cp.async.wait_group %0;" :: "n"(STAGES - 2));
        __syncthreads();
        int ld = s + STAGES - 1;
        if (ld < NT) loadStage(ld & (STAGES - 1), ld * KT);
        asm volatile("cp.async.commit_group;");

        int st = s & (STAGES - 1);
        #pragma unroll
        for (int ks = 0; ks < 2; ks++) {
            int k0 = ks * 16;
            wmma::fragment<wmma::matrix_b, 16, 16, 16, __half, wmma::col_major> bf[2];
            #pragma unroll
            for (int j = 0; j < 2; j++)
                wmma::load_matrix_sync(bf[j], &Bs[st][wn * 32 + j * 16][k0], 40);
            #pragma unroll
            for (int i = 0; i < 4; i++) {
                wmma::fragment<wmma::matrix_a, 16, 16, 16, __half, wmma::row_major> af;
                wmma::load_matrix_sync(af, &As[st][wm * 64 + i * 16][k0], 40);
                #pragma unroll
                for (int j = 0; j < 2; j++)
                    wmma::mma_sync(acc[i][j], af, bf[j], acc[i][j]);
            }
        }
    }

    asm volatile("cp.async.wait_group 0;");
    __syncthreads();
    #pragma unroll
    for (int i = 0; i < 4; i++)
        #pragma unroll
        for (int j = 0; j < 2; j++)
            wmma::store_matrix_sync(&stage[wm * 64 + i * 16][wn * 32 + j * 16],
                                    acc[i][j], 132, wmma::mem_row_major);
    __syncthreads();

    #pragma unroll
    for (int it = 0; it < 16; it++) {
        int idx = tid + it * 256;
        int r = idx >> 5;
        int c4 = (idx & 31) * 4;
        int gc = col0 + c4;
        if (gc >= NCOLS) continue;
        int n = row0 + r;
        float4 v = *(float4*)&stage[r][c4];
        int b = gc / DD;
        int cc = gc - b * DD;
        if (b == 3) {
            if (n < Nn) *(float4*)&out[(size_t)n * DD + cc] = v;
        } else {
            __half2 h0 = __floats2half2_rn(v.x, v.y);
            __half2 h1 = __floats2half2_rn(v.z, v.w);
            uint2 u = make_uint2(*(uint32_t*)&h0, *(uint32_t*)&h1);
            if (b == 0) {
                *(uint2*)&d_Sf[(size_t)n * SFST + cc] = u;          // Q
            } else if (b == 4) {
                *(uint2*)&d_Sf[(size_t)n * SFST + 304 + cc] = u;    // Cd
            } else {
                int off = (b == 1) ? 0 : (b == 2 ? 320 : 640);      // K, V, Cs
                *(uint2*)&d_Sh[(size_t)n * SHST + off + cc] = u;
            }
        }
    }
}

// ---------------- CSR build ----------------
__global__ void zerodeg_kernel(int Nn) {
    int i = blockIdx.x * blockDim.x + threadIdx.x;
    if (i < Nn) d_deg[i] = 0;
}
__global__ void hist_kernel(const int* __restrict__ EI, int Ee) {
    int e = blockIdx.x * blockDim.x + threadIdx.x;
    if (e < Ee) atomicAdd(&d_deg[EI[Ee + e]], 1);
}
__global__ void scan1_kernel(int Nn) {
    __shared__ int sdata[256];
    int t = threadIdx.x;
    int i = blockIdx.x * 256 + t;
    int v = (i < Nn) ? d_deg[i] : 0;
    sdata[t] = v;
    __syncthreads();
    #pragma unroll
    for (int off = 1; off < 256; off <<= 1) {
        int x = (t >= off) ? sdata[t - off] : 0;
        __syncthreads();
        sdata[t] += x;
        __syncthreads();
    }
    if (i < Nn) d_rowptr[i] = sdata[t] - v;
    if (t == 255) d_blksum[blockIdx.x] = sdata[255];
}
__global__ void scan2_kernel(int NB) {
    __shared__ int sdata[256];
    int t = threadIdx.x;
    int v = (t < NB) ? d_blksum[t] : 0;
    sdata[t] = v;
    __syncthreads();
    #pragma unroll
    for (int off = 1; off < 256; off <<= 1) {
        int x = (t >= off) ? sdata[t - off] : 0;
        __syncthreads();
        sdata[t] += x;
        __syncthreads();
    }
    if (t < NB) d_blksum[t] = sdata[t] - v;
}
__global__ void scan3_kernel(int Nn) {
    int i = blockIdx.x * blockDim.x + threadIdx.x;
    if (i >= Nn) return;
    int val = d_rowptr[i] + d_blksum[i >> 8];
    d_rowptr[i] = val;
    d_cursor[i] = val;
    if (i == Nn - 1) d_rowptr[Nn] = val + d_deg[i];
}
__global__ void scatter_kernel(const int* __restrict__ EI, int Ee) {
    int e = blockIdx.x * blockDim.x + threadIdx.x;
    if (e >= Ee) return;
    int dst = EI[Ee + e];
    int pos = atomicAdd(&d_cursor[dst], 1);
    d_edges[pos] = make_int2(EI[e], e);
}

// ---------------- edgeF v4b: fp16 node reads ----------------
__global__ void __launch_bounds__(128, 5) edgeF_kernel(const float* __restrict__ EA,
                                                       const float* __restrict__ Wcls,
                                                       const float* __restrict__ bcls,
                                                       float* __restrict__ out, int Nn) {
    __shared__ float sWc[5 * DD];
    __shared__ float sG[8 * DD];
    __shared__ float2 sW2[DD];
    __shared__ float sBcls[5];
    for (int i = threadIdx.x; i < 5 * DD; i += 128) {
        int k = i / DD, c = i - k * DD;
        sWc[i] = Wcls[c * 5 + k];
    }
    for (int i = threadIdx.x; i < 8 * DD; i += 128) sG[i] = d_G8[i];
    for (int i = threadIdx.x; i < DD; i += 128)
        sW2[i] = make_float2(d_W2f[i], d_W2f[DD + i]);
    if (threadIdx.x < 5) sBcls[threadIdx.x] = bcls[threadIdx.x];
    __syncthreads();

    const uint32_t FULL = 0xffffffffu;
    int lane = threadIdx.x & 31;
    int warp = threadIdx.x >> 5;
    int oh = lane >> 3, oj = lane & 7;
    const float sc = 0.115470053837925152f;  // 1/sqrt(75)

    for (int n = blockIdx.x * 4 + warp; n < Nn; n += gridDim.x * 4) {
        int beg = d_rowptr[n], end = d_rowptr[n + 1];
        const __half* rowQ = d_Sf + (size_t)n * SFST;

        // QG[oh][oj]
        float QG = 0.0f;
        {
            const __half* qb = rowQ + oh * 75;
            const float* gb = sG + oj * DD + oh * 75;
            #pragma unroll 5
            for (int c = 0; c < 75; c++)
                QG = fmaf(__half2float(__ldg(&qb[c])), gb[c], QG);
        }

        // pair ownership: slot s -> cols (2*lane + 64*s, +1)
        float2 q2[5], cd2[5], av[5];
        #pragma unroll
        for (int s = 0; s < 5; s++) {
            int col = 2 * lane + 64 * s;
            bool ok = col < DD;
            if (ok) {
                q2[s]  = __half22float2(*(const __half2*)(rowQ + col));
                cd2[s] = __half22float2(*(const __half2*)(rowQ + 304 + col));
            } else {
                q2[s] = make_float2(0, 0);
                cd2[s] = make_float2(0, 0);
            }
            av[s] = make_float2(0, 0);
        }
        float Tacc = 0.0f;

        for (int p = beg; p < end; p++) {
            int2 se = __ldg(&d_edges[p]);
            const __half* rowS = d_Sh + (size_t)se.x * SHST;
            float4 ea = __ldg((const float4*)&EA[4 * se.y]);

            uint32_t kh[5], vh[5], ch[5];
            #pragma unroll
            for (int s = 0; s < 5; s++) {
                int col = 2 * lane + 64 * s;
                bool ok = col < DD;
                kh[s] = ok ? __ldg((const uint32_t*)(rowS + col)) : 0u;
                vh[s] = ok ? __ldg((const uint32_t*)(rowS + 320 + col)) : 0u;
                ch[s] = ok ? __ldg((const uint32_t*)(rowS + 640 + col)) : 0u;
            }

            float vf0[5], vf1[5];
            float l0 = 0, l1 = 0, l2 = 0, l3 = 0, l4 = 0;
            float a0 = 0, a1 = 0, a2 = 0, a3 = 0;
            #pragma unroll
            for (int s = 0; s < 5; s++) {
                int col = 2 * lane + 64 * s;
                float2 kf = __half22float2(*(__half2*)&kh[s]);
                float2 vf = __half22float2(*(__half2*)&vh[s]);
                float2 cf = __half22float2(*(__half2*)&ch[s]);
                vf0[s] = vf.x; vf1[s] = vf.y;
                if (col < DD) {
                    #pragma unroll
                    for (int i = 0; i < 2; i++) {
                        int c = col + i;
                        float2 w2 = sW2[c];
                        float cdv = i ? cd2[s].y : cd2[s].x;
                        float csv = i ? cf.y : cf.x;
                        float h = fast_tanh(cdv + csv + ea.z * w2.x + ea.w * w2.y);
                        l0 = fmaf(h, sWc[c], l0);
                        l1 = fmaf(h, sWc[DD + c], l1);
                        l2 = fmaf(h, sWc[2 * DD + c], l2);
                        l3 = fmaf(h, sWc[3 * DD + c], l3);
                        l4 = fmaf(h, sWc[4 * DD + c], l4);
                        float pr = (i ? q2[s].y : q2[s].x) * (i ? kf.y : kf.x);
                        if (c < 75) a0 += pr;
                        else if (c < 150) a1 += pr;
                        else if (c < 225) a2 += pr;
                        else a3 += pr;
                    }
                }
            }

            #pragma unroll
            for (int o = 16; o; o >>= 1) {
                l0 += __shfl_xor_sync(FULL, l0, o);
                l1 += __shfl_xor_sync(FULL, l1, o);
                l2 += __shfl_xor_sync(FULL, l2, o);
                l3 += __shfl_xor_sync(FULL, l3, o);
                l4 += __shfl_xor_sync(FULL, l4, o);
                a0 += __shfl_xor_sync(FULL, a0, o);
                a1 += __shfl_xor_sync(FULL, a1, o);
                a2 += __shfl_xor_sync(FULL, a2, o);
                a3 += __shfl_xor_sync(FULL, a3, o);
            }
            l0 += sBcls[0]; l1 += sBcls[1]; l2 += sBcls[2]; l3 += sBcls[3]; l4 += sBcls[4];
            float m = fmaxf(fmaxf(fmaxf(l0, l1), fmaxf(l2, l3)), l4);
            float p0 = __expf(l0 - m), p1 = __expf(l1 - m), p2 = __expf(l2 - m);
            float p3 = __expf(l3 - m), p4 = __expf(l4 - m);
            float inv = 1.0f / (p0 + p1 + p2 + p3 + p4);
            p0 *= inv; p1 *= inv; p2 *= inv; p3 *= inv; p4 *= inv;
            float t0 = ea.x > 0.0f ? 1.0f : 0.0f;
            float t1 = ea.y < 0.0f ? 1.0f : 0.0f;

            float pj = (oj == 0) ? p0 : (oj == 1) ? p1 : (oj == 2) ? p2 : (oj == 3) ? p3
                      : (oj == 4) ? p4 : (oj == 5) ? t0 : (oj == 6) ? t1 : 1.0f;

            float qef = pj * QG;
            qef += __shfl_xor_sync(FULL, qef, 1, 8);
            qef += __shfl_xor_sync(FULL, qef, 2, 8);
            qef += __shfl_xor_sync(FULL, qef, 4, 8);

            float ah = (oh == 0) ? a0 : (oh == 1) ? a1 : (oh == 2) ? a2 : a3;
            float wv = __expf((ah + qef) * sc);

            float w0 = __shfl_sync(FULL, wv, 0);
            float w1 = __shfl_sync(FULL, wv, 8);
            float w2h = __shfl_sync(FULL, wv, 16);
            float w3h = __shfl_sync(FULL, wv, 24);

            Tacc = fmaf(wv, pj, Tacc);

            #pragma unroll
            for (int s = 0; s < 5; s++) {
                int col = 2 * lane + 64 * s;
                if (col < DD) {
                    float wa = col < 75 ? w0 : (col < 150 ? w1 : (col < 225 ? w2h : w3h));
                    int c1 = col + 1;
                    float wb = c1 < 75 ? w0 : (c1 < 150 ? w1 : (c1 < 225 ? w2h : w3h));
                    av[s].x = fmaf(wa, vf0[s], av[s].x);
                    av[s].y = fmaf(wb, vf1[s], av[s].y);
                }
            }
        }

        #pragma unroll
        for (int s = 0; s < 5; s++) {
            int col = 2 * lane + 64 * s;
            bool ok = col < DD;
            #pragma unroll
            for (int i = 0; i < 2; i++) {
                int cc = ok ? col + i : 0;
                int h = cc < 75 ? 0 : (cc < 150 ? 1 : (cc < 225 ? 2 : 3));
                int base = h * 8;
                float add = i ? av[s].y : av[s].x;
                float den = 0.0f;
                #pragma unroll
                for (int jj = 0; jj < 8; jj++) {
                    float tv = __shfl_sync(FULL, Tacc, base + jj);
                    add = fmaf(tv, sG[jj * DD + cc], add);
                    if (jj == 7) den = tv;
                }
                if (ok) {
                    float invd = den > 0.0f ? __fdividef(1.0f, den) : 0.0f;
                    out[(size_t)n * DD + cc] += add * invd;
                }
            }
        }
    }
}

// ---------------- host launcher ----------------
extern "C" void kernel_launch(void* const* d_in, const int* in_sizes, int n_in,
                              void* d_out, int out_size) {
    const float* x     = (const float*)d_in[0];
    const int*   EI    = (const int*)d_in[1];
    const float* EA    = (const float*)d_in[2];
    const float* nrm   = (const float*)d_in[3];
    const float* Wq    = (const float*)d_in[4];
    const float* bq    = (const float*)d_in[5];
    const float* Wk    = (const float*)d_in[6];
    const float* bk    = (const float*)d_in[7];
    const float* Wv    = (const float*)d_in[8];
    const float* bv    = (const float*)d_in[9];
    const float* We    = (const float*)d_in[10];
    const float* Wn    = (const float*)d_in[11];
    const float* bn    = (const float*)d_in[12];
    const float* Wxy   = (const float*)d_in[13];
    const float* bxy   = (const float*)d_in[14];
    const float* Wloc  = (const float*)d_in[15];
    const float* bloc  = (const float*)d_in[16];
    const float* Wobj  = (const float*)d_in[17];
    const float* bobj  = (const float*)d_in[18];
    const float* Wfus  = (const float*)d_in[19];
    const float* bfus  = (const float*)d_in[20];
    const float* Wcls  = (const float*)d_in[21];
    const float* bcls  = (const float*)d_in[22];
    const float* Wskip = (const float*)d_in[23];
    const float* bskip = (const float*)d_in[24];
    const float* vocab = (const float*)d_in[25];

    int Nn = in_sizes[0] / DD;
    int Ee = in_sizes[1] / 2;
    float* out = (float*)d_out;

    static bool init_done = false;
    static cudaStream_t s2;
    static cudaEvent_t ev0, ev1;
    const int gemm_smem = STAGES * (128 * 40 + 128 * 40) * 2;   // 81920 B
    if (!init_done) {
        cudaFuncSetAttribute(gemm_fp16_kernel, cudaFuncAttributeMaxDynamicSharedMemorySize, gemm_smem);
        cudaStreamCreateWithFlags(&s2, cudaStreamNonBlocking);
        cudaEventCreateWithFlags(&ev0, cudaEventDisableTiming);
        cudaEventCreateWithFlags(&ev1, cudaEventDisableTiming);
        init_done = true;
    }

    // fork CSR chain onto s2 (depends only on EI)
    cudaEventRecord(ev0, 0);
    cudaStreamWaitEvent(s2, ev0, 0);
    int NB = (Nn + 255) / 256;
    zerodeg_kernel<<<NB, 256, 0, s2>>>(Nn);
    hist_kernel<<<(Ee + 255) / 256, 256, 0, s2>>>(EI, Ee);
    scan1_kernel<<<NB, 256, 0, s2>>>(Nn);
    scan2_kernel<<<1, 256, 0, s2>>>(NB);
    scan3_kernel<<<NB, 256, 0, s2>>>(Nn);
    scatter_kernel<<<(Ee + 255) / 256, 256, 0, s2>>>(EI, Ee);
    cudaEventRecord(ev1, s2);

    // main chain
    fold1b_kernel<<<DD, 128>>>(Wn, Wxy, Wloc, Wfus, vocab, bxy, bn, bobj, bloc, bfus);
    fold2b_kernel<<<DD, 64>>>(We);
    buildA_kernel<<<(Nn * 304 + 255) / 256, 256>>>(x, nrm, Nn);
    buildW_kernel<<<(NCOLS * 304 + 255) / 256, 256>>>(Wq, Wk, Wv, Wskip, Wobj, bq, bk, bv, bskip);

    dim3 gg(15, MPAD / 128);
    gemm_fp16_kernel<<<gg, 256, gemm_smem>>>(out, Nn);

    cudaStreamWaitEvent(0, ev1, 0);
    edgeF_kernel<<<1480, 128>>>(EA, Wcls, bcls, out, Nn);
}